// round 11
// baseline (speedup 1.0000x reference)
#include <cuda_runtime.h>
#include <cuda_fp16.h>
#include <cstdint>
#include <math.h>

// Problem constants
constexpr int Bb  = 2;
constexpr int Ss  = 2048;
constexpr int Ee  = 2048;
constexpr int Hh  = 32;
constexpr int HKVv= 8;
constexpr int Dd  = 64;
constexpr int MS  = Bb * Ss;      // 4096 rows

// ---------------------------------------------------------------------------
// Scratch. fp16 pairs packed in uint32 (low half = even element).
// ---------------------------------------------------------------------------
__device__ uint32_t s_xh[MS * Ee / 2],  s_xl[MS * Ee / 2];
__device__ uint32_t s_wqh[Ee * Ee / 2];
__device__ uint32_t s_wkh[512 * Ee / 2];
__device__ uint32_t s_wvh[512 * Ee / 2];
__device__ uint32_t s_woh[Ee * Ee / 2];
__device__ uint32_t s_qh[MS * 1024], s_ql[MS * 1024];
__device__ uint32_t s_kh[MS * 256];
__device__ uint32_t s_vh[MS * 256];
__device__ uint32_t s_ah[MS * 1024], s_al[MS * 1024];

// ---------------------------------------------------------------------------
// Helpers
// ---------------------------------------------------------------------------
__device__ __forceinline__ uint32_t smem_u32(const void* p) {
    uint32_t a;
    asm("{ .reg .u64 t; cvta.to.shared.u64 t, %1; cvt.u32.u64 %0, t; }" : "=r"(a) : "l"(p));
    return a;
}

#define LDX4(r0, r1, r2, r3, addr) \
    asm volatile("ldmatrix.sync.aligned.m8n8.x4.shared.b16 {%0,%1,%2,%3}, [%4];" \
        : "=r"(r0), "=r"(r1), "=r"(r2), "=r"(r3) : "r"(addr))

#define LDX4T(r0, r1, r2, r3, addr) \
    asm volatile("ldmatrix.sync.aligned.m8n8.x4.trans.shared.b16 {%0,%1,%2,%3}, [%4];" \
        : "=r"(r0), "=r"(r1), "=r"(r2), "=r"(r3) : "r"(addr))

#define CP_ASYNC16(dst, src) \
    asm volatile("cp.async.cg.shared.global [%0], [%1], 16;" :: "r"(dst), "l"(src))
#define CP_COMMIT() asm volatile("cp.async.commit_group;")
#define CP_WAIT(n)  asm volatile("cp.async.wait_group %0;" :: "n"(n))

__device__ __forceinline__ void mma_f16(float c[4], const uint32_t a[4], const uint32_t b[2]) {
    asm volatile("mma.sync.aligned.m16n8k16.row.col.f32.f16.f16.f32 "
                 "{%0,%1,%2,%3}, {%4,%5,%6,%7}, {%8,%9}, {%0,%1,%2,%3};"
                 : "+f"(c[0]), "+f"(c[1]), "+f"(c[2]), "+f"(c[3])
                 : "r"(a[0]), "r"(a[1]), "r"(a[2]), "r"(a[3]), "r"(b[0]), "r"(b[1]));
}

__device__ __forceinline__ uint32_t packf(float x0, float x1) {
    __half2 h = __floats2half2_rn(x0, x1);
    return *reinterpret_cast<uint32_t*>(&h);
}
__device__ __forceinline__ uint32_t packlo(uint32_t ph, float x0, float x1) {
    __half2 h = *reinterpret_cast<__half2*>(&ph);
    return packf(x0 - __low2float(h), x1 - __high2float(h));
}

// ---------------------------------------------------------------------------
// Fused split kernel: x -> hi+lo; weights -> hi. One launch.
// ---------------------------------------------------------------------------
constexpr int N4_X  = MS * Ee / 4;
constexpr int N4_WQ = Ee * Ee / 4;
constexpr int N4_WK = 512 * Ee / 4;
constexpr int N4_TOT = N4_X + N4_WQ + 2 * N4_WK + N4_WQ;

__global__ void split_all_kernel(
    const float4* __restrict__ x,  const float4* __restrict__ wq,
    const float4* __restrict__ wk, const float4* __restrict__ wv,
    const float4* __restrict__ wo,
    uint2* __restrict__ xh,  uint2* __restrict__ xl,
    uint2* __restrict__ wqh, uint2* __restrict__ wkh,
    uint2* __restrict__ wvh, uint2* __restrict__ woh)
{
    int i = blockIdx.x * blockDim.x + threadIdx.x;
    if (i >= N4_TOT) return;
    const float4* src; uint2* hi; uint2* lo = nullptr; int j = i;
    if (j < N4_X)                   { src = x;  hi = xh;  lo = xl; }
    else if ((j -= N4_X)  < N4_WQ)  { src = wq; hi = wqh; }
    else if ((j -= N4_WQ) < N4_WK)  { src = wk; hi = wkh; }
    else if ((j -= N4_WK) < N4_WK)  { src = wv; hi = wvh; }
    else { j -= N4_WK;                src = wo; hi = woh; }
    float4 f = src[j];
    uint32_t h0 = packf(f.x, f.y), h1 = packf(f.z, f.w);
    hi[j] = make_uint2(h0, h1);
    if (lo) lo[j] = make_uint2(packlo(h0, f.x, f.y), packlo(h1, f.z, f.w));
}

// ---------------------------------------------------------------------------
// fp16 2-term GEMM mainloop v2: warp tile 32x64, BK=64, 3-stage cp.async,
// 1 CTA/SM, register fragment double-buffering across 4 k-chunks per stage.
// smem rows 128B (8 x 16B chunks), swizzle chunk ^= row&7.
// ---------------------------------------------------------------------------
constexpr int GB_TILE  = 128 * 128;        // 16384 per array
constexpr int GB_STAGE = 3 * GB_TILE;      // 49152 (Ah, Al, Bh)
constexpr int GB_SMEM  = 3 * GB_STAGE;     // 147456; 1 CTA/SM

__device__ __forceinline__ uint32_t swz(uint32_t row, uint32_t chunk) {
    return row * 128 + ((chunk ^ (row & 7)) << 4);
}

struct Frags {
    uint32_t bh[8][2];
    uint32_t afh[2][4];
    uint32_t afl[2][4];
};

__device__ __forceinline__ void load_frags(
    Frags& f, uint32_t tb, int kc, int wm, int wn, int lmrow, int lmc)
{
    const uint32_t kchunk = kc * 2 + lmc;
#pragma unroll
    for (int g16 = 0; g16 < 4; ++g16) {
        uint32_t r0, r1, r2, r3;
        LDX4(r0, r1, r2, r3,
             tb + 2 * GB_TILE + swz(wn * 64 + g16 * 16 + lmrow, kchunk));
        f.bh[g16 * 2][0] = r0; f.bh[g16 * 2][1] = r2;
        f.bh[g16 * 2 + 1][0] = r1; f.bh[g16 * 2 + 1][1] = r3;
    }
#pragma unroll
    for (int mt = 0; mt < 2; ++mt) {
        LDX4(f.afh[mt][0], f.afh[mt][1], f.afh[mt][2], f.afh[mt][3],
             tb + swz(wm * 32 + mt * 16 + lmrow, kchunk));
        LDX4(f.afl[mt][0], f.afl[mt][1], f.afl[mt][2], f.afl[mt][3],
             tb + GB_TILE + swz(wm * 32 + mt * 16 + lmrow, kchunk));
    }
}

__device__ __forceinline__ void mma_frags(float acc[2][8][4], const Frags& f)
{
#pragma unroll
    for (int mt = 0; mt < 2; ++mt)
#pragma unroll
        for (int nt = 0; nt < 8; ++nt) {
            mma_f16(acc[mt][nt], f.afh[mt], f.bh[nt]);
            mma_f16(acc[mt][nt], f.afl[mt], f.bh[nt]);
        }
}

__device__ __forceinline__ void gemm_mainloop(
    const char* Ah, const char* Al, const char* Bh,
    int m0, int n0, char* smem, float acc[2][8][4])
{
    const uint32_t sbase = smem_u32(smem);
    const int tid  = threadIdx.x;
    const int wid  = tid >> 5;
    const int lane = tid & 31;
    const int wm = wid & 3;        // 4 m-groups of 32
    const int wn = wid >> 2;       // 2 n-groups of 64
    const int lmrow = lane & 15;
    const int lmc   = lane >> 4;

#pragma unroll
    for (int i = 0; i < 2; ++i)
#pragma unroll
        for (int j = 0; j < 8; ++j)
#pragma unroll
            for (int r = 0; r < 4; ++r) acc[i][j][r] = 0.f;

    // stage issue: 3072 x 16B chunks (BK=64 -> 128 B per row), 12 per thread
    auto issue = [&](int kt, int s) {
#pragma unroll
        for (int c = 0; c < 12; ++c) {
            int ch  = c * 256 + tid;
            int arr = ch >> 10;         // 0=Ah 1=Al 2=Bh
            int r   = (ch >> 3) & 127;
            int c16 = ch & 7;
            const char* g;
            if      (arr == 0) g = Ah + (size_t)(m0 + r) * 4096 + kt * 128 + c16 * 16;
            else if (arr == 1) g = Al + (size_t)(m0 + r) * 4096 + kt * 128 + c16 * 16;
            else               g = Bh + (size_t)(n0 + r) * 4096 + kt * 128 + c16 * 16;
            uint32_t dst = sbase + s * GB_STAGE + arr * GB_TILE + swz(r, c16);
            CP_ASYNC16(dst, g);
        }
        CP_COMMIT();
    };

    issue(0, 0);
    issue(1, 1);

    constexpr int NT = 32;   // 2048 / 64
    Frags fa, fb;
    for (int kt = 0; kt < NT; ++kt) {
        const int s = kt - (kt / 3) * 3;   // kt % 3
        if (kt + 1 < NT) { CP_WAIT(1); } else { CP_WAIT(0); }
        __syncthreads();
        // stage (kt+2)%3 == (kt-1)%3: last read at kt-1, before this barrier
        if (kt + 2 < NT) {
            int sn = s + 2; if (sn >= 3) sn -= 3;
            issue(kt + 2, sn);
        }

        const uint32_t tb = sbase + s * GB_STAGE;
        // 4 k-chunks per stage with register double-buffering
        load_frags(fa, tb, 0, wm, wn, lmrow, lmc);
        load_frags(fb, tb, 1, wm, wn, lmrow, lmc);
        mma_frags(acc, fa);
        load_frags(fa, tb, 2, wm, wn, lmrow, lmc);
        mma_frags(acc, fb);
        load_frags(fb, tb, 3, wm, wn, lmrow, lmc);
        mma_frags(acc, fa);
        mma_frags(acc, fb);
        // no trailing barrier: next iteration's barrier protects reuse
    }
}

// ---------------------------------------------------------------------------
// Fused QKV projection: one launch, 768 CTAs.
// ---------------------------------------------------------------------------
__global__ void __launch_bounds__(256, 1) proj_qkv_kernel(
    const void* xh_, const void* xl_,
    const void* wqh_, const void* wkh_, const void* wvh_,
    const float* __restrict__ cosb, const float* __restrict__ sinb,
    uint32_t* __restrict__ qh, uint32_t* __restrict__ ql,
    uint32_t* __restrict__ kh, uint32_t* __restrict__ vh)
{
    extern __shared__ char smem[];
    const char* xh = (const char*)xh_;
    const char* xl = (const char*)xl_;
    const int id = blockIdx.x;
    const int tid  = threadIdx.x;
    const int wid  = tid >> 5;
    const int lane = tid & 31;
    const int wm = wid & 3;
    const int wn = wid >> 2;
    const int g  = lane >> 2;
    const int tq = lane & 3;

    float acc[2][8][4];

    if (id < 512) {
        // ---- Q projection ----
        const int m0 = (id >> 4) * 128;
        const int n0 = (id & 15) * 128;
        gemm_mainloop(xh, xl, (const char*)wqh_, m0, n0, smem, acc);
        const int head = (n0 + wn * 64) >> 6;
#pragma unroll
        for (int mt = 0; mt < 2; ++mt) {
#pragma unroll
            for (int rr = 0; rr < 2; ++rr) {
                int row = m0 + wm * 32 + mt * 16 + g + rr * 8;
                int s = row & (Ss - 1);
                const float* cb  = cosb + s * 64;
                const float* sb2 = sinb + s * 64;
                uint32_t* qh_p = qh + (size_t)row * 1024 + head * 32;
                uint32_t* ql_p = ql + (size_t)row * 1024 + head * 32;
#pragma unroll
                for (int nt = 0; nt < 4; ++nt) {
                    int d = nt * 8 + tq * 2;
                    float2 c1 = *(const float2*)(cb + d);
                    float2 s1 = *(const float2*)(sb2 + d);
                    float2 c2 = *(const float2*)(cb + d + 32);
                    float2 s2 = *(const float2*)(sb2 + d + 32);
                    float x10 = acc[mt][nt][rr * 2],     x11 = acc[mt][nt][rr * 2 + 1];
                    float x20 = acc[mt][nt + 4][rr * 2], x21 = acc[mt][nt + 4][rr * 2 + 1];
                    float y0 = x10 * c1.x - x20 * s1.x;
                    float y1 = x11 * c1.y - x21 * s1.y;
                    float y2 = x20 * c2.x + x10 * s2.x;
                    float y3 = x21 * c2.y + x11 * s2.y;
                    uint32_t h0 = packf(y0, y1);
                    qh_p[nt * 4 + tq] = h0;
                    ql_p[nt * 4 + tq] = packlo(h0, y0, y1);
                    uint32_t h1 = packf(y2, y3);
                    qh_p[16 + nt * 4 + tq] = h1;
                    ql_p[16 + nt * 4 + tq] = packlo(h1, y2, y3);
                }
            }
        }
    } else if (id < 640) {
        // ---- K projection ----
        const int id2 = id - 512;
        const int m0 = (id2 >> 2) * 128;
        const int n0 = (id2 & 3) * 128;
        gemm_mainloop(xh, xl, (const char*)wkh_, m0, n0, smem, acc);
        const int head = (n0 + wn * 64) >> 6;
#pragma unroll
        for (int mt = 0; mt < 2; ++mt) {
#pragma unroll
            for (int rr = 0; rr < 2; ++rr) {
                int row = m0 + wm * 32 + mt * 16 + g + rr * 8;
                int s = row & (Ss - 1);
                const float* cb  = cosb + s * 64;
                const float* sb2 = sinb + s * 64;
                uint32_t* kh_p = kh + (size_t)row * 256 + head * 32;
#pragma unroll
                for (int nt = 0; nt < 4; ++nt) {
                    int d = nt * 8 + tq * 2;
                    float2 c1 = *(const float2*)(cb + d);
                    float2 s1 = *(const float2*)(sb2 + d);
                    float2 c2 = *(const float2*)(cb + d + 32);
                    float2 s2 = *(const float2*)(sb2 + d + 32);
                    float x10 = acc[mt][nt][rr * 2],     x11 = acc[mt][nt][rr * 2 + 1];
                    float x20 = acc[mt][nt + 4][rr * 2], x21 = acc[mt][nt + 4][rr * 2 + 1];
                    float y0 = x10 * c1.x - x20 * s1.x;
                    float y1 = x11 * c1.y - x21 * s1.y;
                    float y2 = x20 * c2.x + x10 * s2.x;
                    float y3 = x21 * c2.y + x11 * s2.y;
                    kh_p[nt * 4 + tq]      = packf(y0, y1);
                    kh_p[16 + nt * 4 + tq] = packf(y2, y3);
                }
            }
        }
    } else {
        // ---- V projection ----
        const int id2 = id - 640;
        const int m0 = (id2 >> 2) * 128;
        const int n0 = (id2 & 3) * 128;
        gemm_mainloop(xh, xl, (const char*)wvh_, m0, n0, smem, acc);
        const int cp0 = (n0 + wn * 64) >> 1;
#pragma unroll
        for (int mt = 0; mt < 2; ++mt) {
#pragma unroll
            for (int rr = 0; rr < 2; ++rr) {
                int row = m0 + wm * 32 + mt * 16 + g + rr * 8;
                uint32_t* vh_p = vh + (size_t)row * 256 + cp0;
#pragma unroll
                for (int nt = 0; nt < 8; ++nt)
                    vh_p[nt * 4 + tq] = packf(acc[mt][nt][rr * 2], acc[mt][nt][rr * 2 + 1]);
            }
        }
    }
}

// ---------------------------------------------------------------------------
// O projection: fp32 output to d_out.
// ---------------------------------------------------------------------------
__global__ void __launch_bounds__(256, 1) gemm_out_kernel(
    const void* Ah, const void* Al, const void* Bh, float* C)
{
    extern __shared__ char smem[];
    const int tid  = threadIdx.x;
    const int wid  = tid >> 5;
    const int lane = tid & 31;
    const int m0 = blockIdx.y * 128;
    const int n0 = blockIdx.x * 128;
    const int wm = wid & 3;
    const int wn = wid >> 2;
    float acc[2][8][4];
    gemm_mainloop((const char*)Ah, (const char*)Al, (const char*)Bh, m0, n0, smem, acc);
    const int g = lane >> 2;
    const int t = lane & 3;
#pragma unroll
    for (int mt = 0; mt < 2; ++mt) {
#pragma unroll
        for (int nt = 0; nt < 8; ++nt) {
            int r = m0 + wm * 32 + mt * 16 + g;
            int c = n0 + wn * 64 + nt * 8 + t * 2;
            *(float2*)(C + (size_t)r * 2048 + c)       = make_float2(acc[mt][nt][0], acc[mt][nt][1]);
            *(float2*)(C + (size_t)(r + 8) * 2048 + c) = make_float2(acc[mt][nt][2], acc[mt][nt][3]);
        }
    }
}

// ---------------------------------------------------------------------------
// Flash attention, fp16 2-term, 3-stage KV cp.async (unchanged from R10).
// ---------------------------------------------------------------------------
constexpr int AROW   = 144;
constexpr int A_QH   = 0;
constexpr int A_QL   = A_QH + 128 * AROW;
constexpr int A_KV0  = A_QL + 128 * AROW;      // 36864
constexpr int KV_ARR = 64 * AROW;              // 9216 (KH, VH)
constexpr int KVSTAGE = 2 * KV_ARR;            // 18432
constexpr int A_SMEM  = A_KV0 + 3 * KVSTAGE;   // 92160

__global__ void __launch_bounds__(256, 1) attn_mma_kernel(
    const uint32_t* __restrict__ qh_g, const uint32_t* __restrict__ ql_g,
    const uint32_t* __restrict__ kh_g, const uint32_t* __restrict__ vh_g,
    uint32_t* __restrict__ ah_g, uint32_t* __restrict__ al_g)
{
    extern __shared__ char sm[];
    const uint32_t sb = smem_u32(sm);
    const int tid  = threadIdx.x;
    const int wid  = tid >> 5;
    const int lane = tid & 31;
    const int q0 = blockIdx.x * 128;
    const int h  = blockIdx.y;
    const int b  = blockIdx.z;
    const int hkv = h >> 2;

    const int lmrow  = lane & 15;
    const int lmk    = (lane >> 4) * 16;

    auto issue_kv = [&](int t, int s) {
#pragma unroll
        for (int c = 0; c < 4; ++c) {
            int ch  = c * 256 + tid;
            int arr = ch >> 9;
            int r   = (ch >> 3) & 63;
            int c16 = ch & 7;
            const uint32_t* gsrc = arr ? vh_g : kh_g;
            const char* g = (const char*)gsrc
                + ((size_t)(b * Ss + t * 64 + r) * 256 + hkv * 32) * 4 + c16 * 16;
            uint32_t dst = sb + A_KV0 + s * KVSTAGE + arr * KV_ARR + r * AROW + c16 * 16;
            CP_ASYNC16(dst, g);
        }
        CP_COMMIT();
    };

    issue_kv(0, 0);
    issue_kv(1, 1);

#pragma unroll
    for (int c = 0; c < 8; ++c) {
        int ch  = c * 256 + tid;
        int arr = ch >> 10;
        int r   = (ch >> 3) & 127;
        int c16 = ch & 7;
        const char* src = (const char*)(arr ? ql_g : qh_g)
            + ((size_t)(b * Ss + q0 + r) * 1024 + h * 32) * 4 + c16 * 16;
        *(uint4*)(sm + (arr ? A_QL : A_QH) + r * AROW + c16 * 16) = *(const uint4*)src;
    }
    __syncthreads();

    uint32_t qfh[4][4], qfl[4][4];
#pragma unroll
    for (int kd = 0; kd < 4; ++kd) {
        LDX4(qfh[kd][0], qfh[kd][1], qfh[kd][2], qfh[kd][3],
             sb + A_QH + (uint32_t)(wid * 16 + lmrow) * AROW + kd * 32 + lmk);
        LDX4(qfl[kd][0], qfl[kd][1], qfl[kd][2], qfl[kd][3],
             sb + A_QL + (uint32_t)(wid * 16 + lmrow) * AROW + kd * 32 + lmk);
    }

    float o[8][4];
#pragma unroll
    for (int j = 0; j < 8; ++j)
#pragma unroll
        for (int r = 0; r < 4; ++r) o[j][r] = 0.f;
    float mstat[2] = {-1e30f, -1e30f};
    float lstat[2] = {0.f, 0.f};

    constexpr int NTT = Ss / 64;   // 32
    int s3 = 0;
    for (int t = 0; t < NTT; ++t) {
        if (t + 1 < NTT) { CP_WAIT(1); } else { CP_WAIT(0); }
        __syncthreads();
        if (t + 2 < NTT) {
            int sn = s3 + 2; if (sn >= 3) sn -= 3;
            issue_kv(t + 2, sn);
        }

        const uint32_t kvb = sb + A_KV0 + s3 * KVSTAGE;

        float sreg[8][4];
#pragma unroll
        for (int j = 0; j < 8; ++j)
#pragma unroll
            for (int r = 0; r < 4; ++r) sreg[j][r] = 0.f;

#pragma unroll
        for (int kd = 0; kd < 4; ++kd) {
#pragma unroll
            for (int j16 = 0; j16 < 4; ++j16) {
                uint32_t h0, h1, h2, h3;
                LDX4(h0, h1, h2, h3,
                     kvb + (uint32_t)(j16 * 16 + lmrow) * AROW + kd * 32 + lmk);
                uint32_t bh0[2] = {h0, h2}, bh1[2] = {h1, h3};
                mma_f16(sreg[2 * j16],     qfh[kd], bh0);
                mma_f16(sreg[2 * j16],     qfl[kd], bh0);
                mma_f16(sreg[2 * j16 + 1], qfh[kd], bh1);
                mma_f16(sreg[2 * j16 + 1], qfl[kd], bh1);
            }
        }

#pragma unroll
        for (int hf = 0; hf < 2; ++hf) {
            float mx = -1e30f;
#pragma unroll
            for (int j = 0; j < 8; ++j) {
                sreg[j][hf * 2]     *= 0.125f;
                sreg[j][hf * 2 + 1] *= 0.125f;
                mx = fmaxf(mx, fmaxf(sreg[j][hf * 2], sreg[j][hf * 2 + 1]));
            }
            mx = fmaxf(mx, __shfl_xor_sync(0xffffffffu, mx, 1));
            mx = fmaxf(mx, __shfl_xor_sync(0xffffffffu, mx, 2));
            float mnew = fmaxf(mstat[hf], mx);
            float corr = __expf(mstat[hf] - mnew);
            float sum = 0.f;
#pragma unroll
            for (int j = 0; j < 8; ++j) {
                sreg[j][hf * 2]     = __expf(sreg[j][hf * 2] - mnew);
                sreg[j][hf * 2 + 1] = __expf(sreg[j][hf * 2 + 1] - mnew);
                sum += sreg[j][hf * 2] + sreg[j][hf * 2 + 1];
            }
            sum += __shfl_xor_sync(0xffffffffu, sum, 1);
            sum += __shfl_xor_sync(0xffffffffu, sum, 2);
            lstat[hf] = lstat[hf] * corr + sum;
            mstat[hf] = mnew;
#pragma unroll
            for (int j = 0; j < 8; ++j) {
                o[j][hf * 2]     *= corr;
                o[j][hf * 2 + 1] *= corr;
            }
        }

#pragma unroll
        for (int kk = 0; kk < 4; ++kk) {
            uint32_t ah[4], al[4];
            ah[0] = packf(sreg[2 * kk][0],     sreg[2 * kk][1]);
            ah[1] = packf(sreg[2 * kk][2],     sreg[2 * kk][3]);
            ah[2] = packf(sreg[2 * kk + 1][0], sreg[2 * kk + 1][1]);
            ah[3] = packf(sreg[2 * kk + 1][2], sreg[2 * kk + 1][3]);
            al[0] = packlo(ah[0], sreg[2 * kk][0],     sreg[2 * kk][1]);
            al[1] = packlo(ah[1], sreg[2 * kk][2],     sreg[2 * kk][3]);
            al[2] = packlo(ah[2], sreg[2 * kk + 1][0], sreg[2 * kk + 1][1]);
            al[3] = packlo(ah[3], sreg[2 * kk + 1][2], sreg[2 * kk + 1][3]);
#pragma unroll
            for (int j = 0; j < 4; ++j) {
                uint32_t vh0, vh1, vh2, vh3;
                LDX4T(vh0, vh1, vh2, vh3,
                      kvb + KV_ARR + (uint32_t)(kk * 16 + lmrow) * AROW + j * 32 + lmk);
                uint32_t bh0[2] = {vh0, vh1}, bh1[2] = {vh2, vh3};
                mma_f16(o[2 * j],     ah, bh0);
                mma_f16(o[2 * j],     al, bh0);
                mma_f16(o[2 * j + 1], ah, bh1);
                mma_f16(o[2 * j + 1], al, bh1);
            }
        }
        if (++s3 == 3) s3 = 0;
    }

    const int g  = lane >> 2;
    const int tt = lane & 3;
    const float inv0 = 1.f / lstat[0];
    const float inv1 = 1.f / lstat[1];
    const int mrow = q0 + wid * 16 + g;
    uint32_t* ah0 = ah_g + (size_t)(b * Ss + mrow) * 1024 + h * 32;
    uint32_t* al0 = al_g + (size_t)(b * Ss + mrow) * 1024 + h * 32;
    uint32_t* ah1 = ah0 + (size_t)8 * 1024;
    uint32_t* al1 = al0 + (size_t)8 * 1024;
#pragma unroll
    for (int j = 0; j < 8; ++j) {
        float y0 = o[j][0] * inv0, y1 = o[j][1] * inv0;
        uint32_t ph = packf(y0, y1);
        ah0[j * 4 + tt] = ph;
        al0[j * 4 + tt] = packlo(ph, y0, y1);
        float y2 = o[j][2] * inv1, y3 = o[j][3] * inv1;
        uint32_t ph2 = packf(y2, y3);
        ah1[j * 4 + tt] = ph2;
        al1[j * 4 + tt] = packlo(ph2, y2, y3);
    }
}

// ---------------------------------------------------------------------------
extern "C" void kernel_launch(void* const* d_in, const int* in_sizes, int n_in,
                              void* d_out, int out_size)
{
    (void)in_sizes; (void)n_in; (void)out_size;
    const float* x    = (const float*)d_in[0];
    const float* cosb = (const float*)d_in[1];
    const float* sinb = (const float*)d_in[2];
    const float* Wq   = (const float*)d_in[3];
    const float* Wk   = (const float*)d_in[4];
    const float* Wv   = (const float*)d_in[5];
    const float* Wo   = (const float*)d_in[6];
    float* out = (float*)d_out;

    void *xh, *xl, *wqh, *wkh, *wvh, *woh;
    void *qhp, *qlp, *khp, *vhp, *ahp, *alp;
    cudaGetSymbolAddress(&xh, s_xh);   cudaGetSymbolAddress(&xl, s_xl);
    cudaGetSymbolAddress(&wqh, s_wqh); cudaGetSymbolAddress(&wkh, s_wkh);
    cudaGetSymbolAddress(&wvh, s_wvh); cudaGetSymbolAddress(&woh, s_woh);
    cudaGetSymbolAddress(&qhp, s_qh);  cudaGetSymbolAddress(&qlp, s_ql);
    cudaGetSymbolAddress(&khp, s_kh);  cudaGetSymbolAddress(&vhp, s_vh);
    cudaGetSymbolAddress(&ahp, s_ah);  cudaGetSymbolAddress(&alp, s_al);

    cudaFuncSetAttribute(proj_qkv_kernel, cudaFuncAttributeMaxDynamicSharedMemorySize, GB_SMEM);
    cudaFuncSetAttribute(gemm_out_kernel, cudaFuncAttributeMaxDynamicSharedMemorySize, GB_SMEM);
    cudaFuncSetAttribute(attn_mma_kernel, cudaFuncAttributeMaxDynamicSharedMemorySize, A_SMEM);

    // 1) pre-split x (hi+lo) and weights (hi)
    split_all_kernel<<<(N4_TOT + 255) / 256, 256>>>(
        (const float4*)x, (const float4*)Wq, (const float4*)Wk,
        (const float4*)Wv, (const float4*)Wo,
        (uint2*)xh, (uint2*)xl, (uint2*)wqh, (uint2*)wkh,
        (uint2*)wvh, (uint2*)woh);

    // 2) fused QKV projections with rope/split epilogues (one launch)
    proj_qkv_kernel<<<768, 256, GB_SMEM>>>(
        xh, xl, wqh, wkh, wvh, cosb, sinb,
        (uint32_t*)qhp, (uint32_t*)qlp, (uint32_t*)khp, (uint32_t*)vhp);

    // 3) attention
    attn_mma_kernel<<<dim3(16, 32, 2), 256, A_SMEM>>>(
        (const uint32_t*)qhp, (const uint32_t*)qlp,
        (const uint32_t*)khp, (const uint32_t*)vhp,
        (uint32_t*)ahp, (uint32_t*)alp);

    // 4) output projection
    gemm_out_kernel<<<dim3(16, 32), 256, GB_SMEM>>>(ahp, alp, woh, out);
}

// round 12
// speedup vs baseline: 1.0887x; 1.0887x over previous
#include <cuda_runtime.h>
#include <cuda_fp16.h>
#include <cstdint>
#include <math.h>

// Problem constants
constexpr int Bb  = 2;
constexpr int Ss  = 2048;
constexpr int Ee  = 2048;
constexpr int Hh  = 32;
constexpr int HKVv= 8;
constexpr int Dd  = 64;
constexpr int MS  = Bb * Ss;      // 4096 rows

// ---------------------------------------------------------------------------
// Scratch. fp16 pairs packed in uint32 (low half = even element).
// ---------------------------------------------------------------------------
__device__ uint32_t s_xh[MS * Ee / 2],  s_xl[MS * Ee / 2];
__device__ uint32_t s_wqh[Ee * Ee / 2];
__device__ uint32_t s_wkh[512 * Ee / 2];
__device__ uint32_t s_wvh[512 * Ee / 2];
__device__ uint32_t s_woh[Ee * Ee / 2];
__device__ uint32_t s_qh[MS * 1024], s_ql[MS * 1024];
__device__ uint32_t s_kh[MS * 256];
__device__ uint32_t s_vh[MS * 256];
__device__ uint32_t s_ah[MS * 1024], s_al[MS * 1024];

// ---------------------------------------------------------------------------
// Helpers
// ---------------------------------------------------------------------------
__device__ __forceinline__ uint32_t smem_u32(const void* p) {
    uint32_t a;
    asm("{ .reg .u64 t; cvta.to.shared.u64 t, %1; cvt.u32.u64 %0, t; }" : "=r"(a) : "l"(p));
    return a;
}

#define LDX4(r0, r1, r2, r3, addr) \
    asm volatile("ldmatrix.sync.aligned.m8n8.x4.shared.b16 {%0,%1,%2,%3}, [%4];" \
        : "=r"(r0), "=r"(r1), "=r"(r2), "=r"(r3) : "r"(addr))

#define LDX4T(r0, r1, r2, r3, addr) \
    asm volatile("ldmatrix.sync.aligned.m8n8.x4.trans.shared.b16 {%0,%1,%2,%3}, [%4];" \
        : "=r"(r0), "=r"(r1), "=r"(r2), "=r"(r3) : "r"(addr))

#define CP_ASYNC16(dst, src) \
    asm volatile("cp.async.cg.shared.global [%0], [%1], 16;" :: "r"(dst), "l"(src))
#define CP_COMMIT() asm volatile("cp.async.commit_group;")
#define CP_WAIT(n)  asm volatile("cp.async.wait_group %0;" :: "n"(n))

__device__ __forceinline__ void mma_f16(float c[4], const uint32_t a[4], const uint32_t b[2]) {
    asm volatile("mma.sync.aligned.m16n8k16.row.col.f32.f16.f16.f32 "
                 "{%0,%1,%2,%3}, {%4,%5,%6,%7}, {%8,%9}, {%0,%1,%2,%3};"
                 : "+f"(c[0]), "+f"(c[1]), "+f"(c[2]), "+f"(c[3])
                 : "r"(a[0]), "r"(a[1]), "r"(a[2]), "r"(a[3]), "r"(b[0]), "r"(b[1]));
}

__device__ __forceinline__ uint32_t packf(float x0, float x1) {
    __half2 h = __floats2half2_rn(x0, x1);
    return *reinterpret_cast<uint32_t*>(&h);
}
__device__ __forceinline__ uint32_t packlo(uint32_t ph, float x0, float x1) {
    __half2 h = *reinterpret_cast<__half2*>(&ph);
    return packf(x0 - __low2float(h), x1 - __high2float(h));
}

// ---------------------------------------------------------------------------
// Fused split kernel: x -> hi+lo; weights -> hi. One launch.
// ---------------------------------------------------------------------------
constexpr int N4_X  = MS * Ee / 4;
constexpr int N4_WQ = Ee * Ee / 4;
constexpr int N4_WK = 512 * Ee / 4;
constexpr int N4_TOT = N4_X + N4_WQ + 2 * N4_WK + N4_WQ;

__global__ void split_all_kernel(
    const float4* __restrict__ x,  const float4* __restrict__ wq,
    const float4* __restrict__ wk, const float4* __restrict__ wv,
    const float4* __restrict__ wo,
    uint2* __restrict__ xh,  uint2* __restrict__ xl,
    uint2* __restrict__ wqh, uint2* __restrict__ wkh,
    uint2* __restrict__ wvh, uint2* __restrict__ woh)
{
    int i = blockIdx.x * blockDim.x + threadIdx.x;
    if (i >= N4_TOT) return;
    const float4* src; uint2* hi; uint2* lo = nullptr; int j = i;
    if (j < N4_X)                   { src = x;  hi = xh;  lo = xl; }
    else if ((j -= N4_X)  < N4_WQ)  { src = wq; hi = wqh; }
    else if ((j -= N4_WQ) < N4_WK)  { src = wk; hi = wkh; }
    else if ((j -= N4_WK) < N4_WK)  { src = wv; hi = wvh; }
    else { j -= N4_WK;                src = wo; hi = woh; }
    float4 f = src[j];
    uint32_t h0 = packf(f.x, f.y), h1 = packf(f.z, f.w);
    hi[j] = make_uint2(h0, h1);
    if (lo) lo[j] = make_uint2(packlo(h0, f.x, f.y), packlo(h1, f.z, f.w));
}

// ---------------------------------------------------------------------------
// fp16 2-term GEMM mainloop (R10 config): warp tile 32x64, BK=32, 4-stage
// cp.async, 2 CTAs/SM, single sync per stage. smem rows 64B, XOR swizzle.
// ---------------------------------------------------------------------------
constexpr int GB_TILE  = 128 * 64;         // 8192
constexpr int GB_STAGE = 3 * GB_TILE;      // 24576 (Ah, Al, Bh)
constexpr int GB_SMEM  = 4 * GB_STAGE;     // 98304; 2 CTAs/SM

__device__ __forceinline__ uint32_t swz(uint32_t row, uint32_t chunk) {
    return row * 64 + ((chunk ^ ((row >> 1) & 3)) << 4);
}

__device__ __forceinline__ void gemm_mainloop(
    const char* Ah, const char* Al, const char* Bh,
    int m0, int n0, char* smem, float acc[2][8][4])
{
    const uint32_t sbase = smem_u32(smem);
    const int tid  = threadIdx.x;
    const int wid  = tid >> 5;
    const int lane = tid & 31;
    const int wm = wid & 3;        // 4 m-groups of 32
    const int wn = wid >> 2;       // 2 n-groups of 64
    const int lmrow = lane & 15;
    const int lmc   = lane >> 4;

#pragma unroll
    for (int i = 0; i < 2; ++i)
#pragma unroll
        for (int j = 0; j < 8; ++j)
#pragma unroll
            for (int r = 0; r < 4; ++r) acc[i][j][r] = 0.f;

    auto issue = [&](int kt, int s) {
#pragma unroll
        for (int c = 0; c < 6; ++c) {
            int ch  = c * 256 + tid;
            int arr = ch >> 9;          // 0=Ah 1=Al 2=Bh
            int r   = (ch >> 2) & 127;
            int c16 = ch & 3;
            const char* g;
            if      (arr == 0) g = Ah + (size_t)(m0 + r) * 4096 + kt * 64 + c16 * 16;
            else if (arr == 1) g = Al + (size_t)(m0 + r) * 4096 + kt * 64 + c16 * 16;
            else               g = Bh + (size_t)(n0 + r) * 4096 + kt * 64 + c16 * 16;
            uint32_t dst = sbase + s * GB_STAGE + arr * GB_TILE + swz(r, c16);
            CP_ASYNC16(dst, g);
        }
        CP_COMMIT();
    };

    issue(0, 0);
    issue(1, 1);
    issue(2, 2);

    constexpr int NT = 64;
    for (int kt = 0; kt < NT; ++kt) {
        const int s = kt & 3;
        if (kt + 2 < NT)      { CP_WAIT(2); }
        else if (kt + 1 < NT) { CP_WAIT(1); }
        else                  { CP_WAIT(0); }
        __syncthreads();
        if (kt + 3 < NT) issue(kt + 3, (kt + 3) & 3);

        const uint32_t tb = sbase + s * GB_STAGE;
#pragma unroll
        for (int ks = 0; ks < 2; ++ks) {
            const uint32_t kchunk = ks * 2 + lmc;
            uint32_t bh[8][2];
#pragma unroll
            for (int g16 = 0; g16 < 4; ++g16) {
                uint32_t r0, r1, r2, r3;
                LDX4(r0, r1, r2, r3,
                     tb + 2 * GB_TILE + swz(wn * 64 + g16 * 16 + lmrow, kchunk));
                bh[g16 * 2][0] = r0; bh[g16 * 2][1] = r2;
                bh[g16 * 2 + 1][0] = r1; bh[g16 * 2 + 1][1] = r3;
            }
            uint32_t afh[2][4], afl[2][4];
#pragma unroll
            for (int mt = 0; mt < 2; ++mt) {
                LDX4(afh[mt][0], afh[mt][1], afh[mt][2], afh[mt][3],
                     tb + swz(wm * 32 + mt * 16 + lmrow, kchunk));
                LDX4(afl[mt][0], afl[mt][1], afl[mt][2], afl[mt][3],
                     tb + GB_TILE + swz(wm * 32 + mt * 16 + lmrow, kchunk));
            }
#pragma unroll
            for (int mt = 0; mt < 2; ++mt)
#pragma unroll
                for (int nt = 0; nt < 8; ++nt) {
                    mma_f16(acc[mt][nt], afh[mt], bh[nt]);
                    mma_f16(acc[mt][nt], afl[mt], bh[nt]);
                }
        }
    }
}

// ---------------------------------------------------------------------------
// Fused QKV projection: one launch, 768 CTAs. Q epilogue folds the 0.125
// softmax scale (exact power of 2) into the packed q.
// ---------------------------------------------------------------------------
__global__ void __launch_bounds__(256, 2) proj_qkv_kernel(
    const void* xh_, const void* xl_,
    const void* wqh_, const void* wkh_, const void* wvh_,
    const float* __restrict__ cosb, const float* __restrict__ sinb,
    uint32_t* __restrict__ qh, uint32_t* __restrict__ ql,
    uint32_t* __restrict__ kh, uint32_t* __restrict__ vh)
{
    extern __shared__ char smem[];
    const char* xh = (const char*)xh_;
    const char* xl = (const char*)xl_;
    const int id = blockIdx.x;
    const int tid  = threadIdx.x;
    const int wid  = tid >> 5;
    const int lane = tid & 31;
    const int wm = wid & 3;
    const int wn = wid >> 2;
    const int g  = lane >> 2;
    const int tq = lane & 3;

    float acc[2][8][4];

    if (id < 512) {
        // ---- Q projection (scaled by 0.125) ----
        const int m0 = (id >> 4) * 128;
        const int n0 = (id & 15) * 128;
        gemm_mainloop(xh, xl, (const char*)wqh_, m0, n0, smem, acc);
        const int head = (n0 + wn * 64) >> 6;
#pragma unroll
        for (int mt = 0; mt < 2; ++mt) {
#pragma unroll
            for (int rr = 0; rr < 2; ++rr) {
                int row = m0 + wm * 32 + mt * 16 + g + rr * 8;
                int s = row & (Ss - 1);
                const float* cb  = cosb + s * 64;
                const float* sb2 = sinb + s * 64;
                uint32_t* qh_p = qh + (size_t)row * 1024 + head * 32;
                uint32_t* ql_p = ql + (size_t)row * 1024 + head * 32;
#pragma unroll
                for (int nt = 0; nt < 4; ++nt) {
                    int d = nt * 8 + tq * 2;
                    float2 c1 = *(const float2*)(cb + d);
                    float2 s1 = *(const float2*)(sb2 + d);
                    float2 c2 = *(const float2*)(cb + d + 32);
                    float2 s2 = *(const float2*)(sb2 + d + 32);
                    float x10 = acc[mt][nt][rr * 2],     x11 = acc[mt][nt][rr * 2 + 1];
                    float x20 = acc[mt][nt + 4][rr * 2], x21 = acc[mt][nt + 4][rr * 2 + 1];
                    float y0 = (x10 * c1.x - x20 * s1.x) * 0.125f;
                    float y1 = (x11 * c1.y - x21 * s1.y) * 0.125f;
                    float y2 = (x20 * c2.x + x10 * s2.x) * 0.125f;
                    float y3 = (x21 * c2.y + x11 * s2.y) * 0.125f;
                    uint32_t h0 = packf(y0, y1);
                    qh_p[nt * 4 + tq] = h0;
                    ql_p[nt * 4 + tq] = packlo(h0, y0, y1);
                    uint32_t h1 = packf(y2, y3);
                    qh_p[16 + nt * 4 + tq] = h1;
                    ql_p[16 + nt * 4 + tq] = packlo(h1, y2, y3);
                }
            }
        }
    } else if (id < 640) {
        // ---- K projection ----
        const int id2 = id - 512;
        const int m0 = (id2 >> 2) * 128;
        const int n0 = (id2 & 3) * 128;
        gemm_mainloop(xh, xl, (const char*)wkh_, m0, n0, smem, acc);
        const int head = (n0 + wn * 64) >> 6;
#pragma unroll
        for (int mt = 0; mt < 2; ++mt) {
#pragma unroll
            for (int rr = 0; rr < 2; ++rr) {
                int row = m0 + wm * 32 + mt * 16 + g + rr * 8;
                int s = row & (Ss - 1);
                const float* cb  = cosb + s * 64;
                const float* sb2 = sinb + s * 64;
                uint32_t* kh_p = kh + (size_t)row * 256 + head * 32;
#pragma unroll
                for (int nt = 0; nt < 4; ++nt) {
                    int d = nt * 8 + tq * 2;
                    float2 c1 = *(const float2*)(cb + d);
                    float2 s1 = *(const float2*)(sb2 + d);
                    float2 c2 = *(const float2*)(cb + d + 32);
                    float2 s2 = *(const float2*)(sb2 + d + 32);
                    float x10 = acc[mt][nt][rr * 2],     x11 = acc[mt][nt][rr * 2 + 1];
                    float x20 = acc[mt][nt + 4][rr * 2], x21 = acc[mt][nt + 4][rr * 2 + 1];
                    float y0 = x10 * c1.x - x20 * s1.x;
                    float y1 = x11 * c1.y - x21 * s1.y;
                    float y2 = x20 * c2.x + x10 * s2.x;
                    float y3 = x21 * c2.y + x11 * s2.y;
                    kh_p[nt * 4 + tq]      = packf(y0, y1);
                    kh_p[16 + nt * 4 + tq] = packf(y2, y3);
                }
            }
        }
    } else {
        // ---- V projection ----
        const int id2 = id - 640;
        const int m0 = (id2 >> 2) * 128;
        const int n0 = (id2 & 3) * 128;
        gemm_mainloop(xh, xl, (const char*)wvh_, m0, n0, smem, acc);
        const int cp0 = (n0 + wn * 64) >> 1;
#pragma unroll
        for (int mt = 0; mt < 2; ++mt) {
#pragma unroll
            for (int rr = 0; rr < 2; ++rr) {
                int row = m0 + wm * 32 + mt * 16 + g + rr * 8;
                uint32_t* vh_p = vh + (size_t)row * 256 + cp0;
#pragma unroll
                for (int nt = 0; nt < 8; ++nt)
                    vh_p[nt * 4 + tq] = packf(acc[mt][nt][rr * 2], acc[mt][nt][rr * 2 + 1]);
            }
        }
    }
}

// ---------------------------------------------------------------------------
// O projection: fp32 output to d_out.
// ---------------------------------------------------------------------------
__global__ void __launch_bounds__(256, 2) gemm_out_kernel(
    const void* Ah, const void* Al, const void* Bh, float* C)
{
    extern __shared__ char smem[];
    const int tid  = threadIdx.x;
    const int wid  = tid >> 5;
    const int lane = tid & 31;
    const int m0 = blockIdx.y * 128;
    const int n0 = blockIdx.x * 128;
    const int wm = wid & 3;
    const int wn = wid >> 2;
    float acc[2][8][4];
    gemm_mainloop((const char*)Ah, (const char*)Al, (const char*)Bh, m0, n0, smem, acc);
    const int g = lane >> 2;
    const int t = lane & 3;
#pragma unroll
    for (int mt = 0; mt < 2; ++mt) {
#pragma unroll
        for (int nt = 0; nt < 8; ++nt) {
            int r = m0 + wm * 32 + mt * 16 + g;
            int c = n0 + wn * 64 + nt * 8 + t * 2;
            *(float2*)(C + (size_t)r * 2048 + c)       = make_float2(acc[mt][nt][0], acc[mt][nt][1]);
            *(float2*)(C + (size_t)(r + 8) * 2048 + c) = make_float2(acc[mt][nt][2], acc[mt][nt][3]);
        }
    }
}

// ---------------------------------------------------------------------------
// Flash attention. QK: 2-term (Qh+Ql)*Kh. PV: single-term Ph*Vh.
// Q pre-scaled by 0.125. 3-stage KV cp.async, single sync per tile.
// ---------------------------------------------------------------------------
constexpr int AROW   = 144;
constexpr int A_QH   = 0;
constexpr int A_QL   = A_QH + 128 * AROW;
constexpr int A_KV0  = A_QL + 128 * AROW;      // 36864
constexpr int KV_ARR = 64 * AROW;              // 9216 (KH, VH)
constexpr int KVSTAGE = 2 * KV_ARR;            // 18432
constexpr int A_SMEM  = A_KV0 + 3 * KVSTAGE;   // 92160

__global__ void __launch_bounds__(256, 1) attn_mma_kernel(
    const uint32_t* __restrict__ qh_g, const uint32_t* __restrict__ ql_g,
    const uint32_t* __restrict__ kh_g, const uint32_t* __restrict__ vh_g,
    uint32_t* __restrict__ ah_g, uint32_t* __restrict__ al_g)
{
    extern __shared__ char sm[];
    const uint32_t sb = smem_u32(sm);
    const int tid  = threadIdx.x;
    const int wid  = tid >> 5;
    const int lane = tid & 31;
    const int q0 = blockIdx.x * 128;
    const int h  = blockIdx.y;
    const int b  = blockIdx.z;
    const int hkv = h >> 2;

    const int lmrow  = lane & 15;
    const int lmk    = (lane >> 4) * 16;

    auto issue_kv = [&](int t, int s) {
#pragma unroll
        for (int c = 0; c < 4; ++c) {
            int ch  = c * 256 + tid;
            int arr = ch >> 9;
            int r   = (ch >> 3) & 63;
            int c16 = ch & 7;
            const uint32_t* gsrc = arr ? vh_g : kh_g;
            const char* g = (const char*)gsrc
                + ((size_t)(b * Ss + t * 64 + r) * 256 + hkv * 32) * 4 + c16 * 16;
            uint32_t dst = sb + A_KV0 + s * KVSTAGE + arr * KV_ARR + r * AROW + c16 * 16;
            CP_ASYNC16(dst, g);
        }
        CP_COMMIT();
    };

    issue_kv(0, 0);
    issue_kv(1, 1);

#pragma unroll
    for (int c = 0; c < 8; ++c) {
        int ch  = c * 256 + tid;
        int arr = ch >> 10;
        int r   = (ch >> 3) & 127;
        int c16 = ch & 7;
        const char* src = (const char*)(arr ? ql_g : qh_g)
            + ((size_t)(b * Ss + q0 + r) * 1024 + h * 32) * 4 + c16 * 16;
        *(uint4*)(sm + (arr ? A_QL : A_QH) + r * AROW + c16 * 16) = *(const uint4*)src;
    }
    __syncthreads();

    uint32_t qfh[4][4], qfl[4][4];
#pragma unroll
    for (int kd = 0; kd < 4; ++kd) {
        LDX4(qfh[kd][0], qfh[kd][1], qfh[kd][2], qfh[kd][3],
             sb + A_QH + (uint32_t)(wid * 16 + lmrow) * AROW + kd * 32 + lmk);
        LDX4(qfl[kd][0], qfl[kd][1], qfl[kd][2], qfl[kd][3],
             sb + A_QL + (uint32_t)(wid * 16 + lmrow) * AROW + kd * 32 + lmk);
    }

    float o[8][4];
#pragma unroll
    for (int j = 0; j < 8; ++j)
#pragma unroll
        for (int r = 0; r < 4; ++r) o[j][r] = 0.f;
    float mstat[2] = {-1e30f, -1e30f};
    float lstat[2] = {0.f, 0.f};

    constexpr int NTT = Ss / 64;   // 32
    int s3 = 0;
    for (int t = 0; t < NTT; ++t) {
        if (t + 1 < NTT) { CP_WAIT(1); } else { CP_WAIT(0); }
        __syncthreads();
        if (t + 2 < NTT) {
            int sn = s3 + 2; if (sn >= 3) sn -= 3;
            issue_kv(t + 2, sn);
        }

        const uint32_t kvb = sb + A_KV0 + s3 * KVSTAGE;

        // ---- S = Q K^T (2-term, pre-scaled) ----
        float sreg[8][4];
#pragma unroll
        for (int j = 0; j < 8; ++j)
#pragma unroll
            for (int r = 0; r < 4; ++r) sreg[j][r] = 0.f;

#pragma unroll
        for (int kd = 0; kd < 4; ++kd) {
#pragma unroll
            for (int j16 = 0; j16 < 4; ++j16) {
                uint32_t h0, h1, h2, h3;
                LDX4(h0, h1, h2, h3,
                     kvb + (uint32_t)(j16 * 16 + lmrow) * AROW + kd * 32 + lmk);
                uint32_t bh0[2] = {h0, h2}, bh1[2] = {h1, h3};
                mma_f16(sreg[2 * j16],     qfh[kd], bh0);
                mma_f16(sreg[2 * j16],     qfl[kd], bh0);
                mma_f16(sreg[2 * j16 + 1], qfh[kd], bh1);
                mma_f16(sreg[2 * j16 + 1], qfl[kd], bh1);
            }
        }

        // ---- online softmax (scores already scaled) ----
#pragma unroll
        for (int hf = 0; hf < 2; ++hf) {
            float mx = -1e30f;
#pragma unroll
            for (int j = 0; j < 8; ++j)
                mx = fmaxf(mx, fmaxf(sreg[j][hf * 2], sreg[j][hf * 2 + 1]));
            mx = fmaxf(mx, __shfl_xor_sync(0xffffffffu, mx, 1));
            mx = fmaxf(mx, __shfl_xor_sync(0xffffffffu, mx, 2));
            float mnew = fmaxf(mstat[hf], mx);
            float corr = __expf(mstat[hf] - mnew);
            float sum = 0.f;
#pragma unroll
            for (int j = 0; j < 8; ++j) {
                sreg[j][hf * 2]     = __expf(sreg[j][hf * 2] - mnew);
                sreg[j][hf * 2 + 1] = __expf(sreg[j][hf * 2 + 1] - mnew);
                sum += sreg[j][hf * 2] + sreg[j][hf * 2 + 1];
            }
            sum += __shfl_xor_sync(0xffffffffu, sum, 1);
            sum += __shfl_xor_sync(0xffffffffu, sum, 2);
            lstat[hf] = lstat[hf] * corr + sum;
            mstat[hf] = mnew;
#pragma unroll
            for (int j = 0; j < 8; ++j) {
                o[j][hf * 2]     *= corr;
                o[j][hf * 2 + 1] *= corr;
            }
        }

        // ---- O += P V (single-term Ph*Vh) ----
#pragma unroll
        for (int kk = 0; kk < 4; ++kk) {
            uint32_t ah[4];
            ah[0] = packf(sreg[2 * kk][0],     sreg[2 * kk][1]);
            ah[1] = packf(sreg[2 * kk][2],     sreg[2 * kk][3]);
            ah[2] = packf(sreg[2 * kk + 1][0], sreg[2 * kk + 1][1]);
            ah[3] = packf(sreg[2 * kk + 1][2], sreg[2 * kk + 1][3]);
#pragma unroll
            for (int j = 0; j < 4; ++j) {
                uint32_t vh0, vh1, vh2, vh3;
                LDX4T(vh0, vh1, vh2, vh3,
                      kvb + KV_ARR + (uint32_t)(kk * 16 + lmrow) * AROW + j * 32 + lmk);
                uint32_t bh0[2] = {vh0, vh1}, bh1[2] = {vh2, vh3};
                mma_f16(o[2 * j],     ah, bh0);
                mma_f16(o[2 * j + 1], ah, bh1);
            }
        }
        if (++s3 == 3) s3 = 0;
    }

    const int g  = lane >> 2;
    const int tt = lane & 3;
    const float inv0 = 1.f / lstat[0];
    const float inv1 = 1.f / lstat[1];
    const int mrow = q0 + wid * 16 + g;
    uint32_t* ah0 = ah_g + (size_t)(b * Ss + mrow) * 1024 + h * 32;
    uint32_t* al0 = al_g + (size_t)(b * Ss + mrow) * 1024 + h * 32;
    uint32_t* ah1 = ah0 + (size_t)8 * 1024;
    uint32_t* al1 = al0 + (size_t)8 * 1024;
#pragma unroll
    for (int j = 0; j < 8; ++j) {
        float y0 = o[j][0] * inv0, y1 = o[j][1] * inv0;
        uint32_t ph = packf(y0, y1);
        ah0[j * 4 + tt] = ph;
        al0[j * 4 + tt] = packlo(ph, y0, y1);
        float y2 = o[j][2] * inv1, y3 = o[j][3] * inv1;
        uint32_t ph2 = packf(y2, y3);
        ah1[j * 4 + tt] = ph2;
        al1[j * 4 + tt] = packlo(ph2, y2, y3);
    }
}

// ---------------------------------------------------------------------------
extern "C" void kernel_launch(void* const* d_in, const int* in_sizes, int n_in,
                              void* d_out, int out_size)
{
    (void)in_sizes; (void)n_in; (void)out_size;
    const float* x    = (const float*)d_in[0];
    const float* cosb = (const float*)d_in[1];
    const float* sinb = (const float*)d_in[2];
    const float* Wq   = (const float*)d_in[3];
    const float* Wk   = (const float*)d_in[4];
    const float* Wv   = (const float*)d_in[5];
    const float* Wo   = (const float*)d_in[6];
    float* out = (float*)d_out;

    void *xh, *xl, *wqh, *wkh, *wvh, *woh;
    void *qhp, *qlp, *khp, *vhp, *ahp, *alp;
    cudaGetSymbolAddress(&xh, s_xh);   cudaGetSymbolAddress(&xl, s_xl);
    cudaGetSymbolAddress(&wqh, s_wqh); cudaGetSymbolAddress(&wkh, s_wkh);
    cudaGetSymbolAddress(&wvh, s_wvh); cudaGetSymbolAddress(&woh, s_woh);
    cudaGetSymbolAddress(&qhp, s_qh);  cudaGetSymbolAddress(&qlp, s_ql);
    cudaGetSymbolAddress(&khp, s_kh);  cudaGetSymbolAddress(&vhp, s_vh);
    cudaGetSymbolAddress(&ahp, s_ah);  cudaGetSymbolAddress(&alp, s_al);

    cudaFuncSetAttribute(proj_qkv_kernel, cudaFuncAttributeMaxDynamicSharedMemorySize, GB_SMEM);
    cudaFuncSetAttribute(gemm_out_kernel, cudaFuncAttributeMaxDynamicSharedMemorySize, GB_SMEM);
    cudaFuncSetAttribute(attn_mma_kernel, cudaFuncAttributeMaxDynamicSharedMemorySize, A_SMEM);

    // 1) pre-split x (hi+lo) and weights (hi)
    split_all_kernel<<<(N4_TOT + 255) / 256, 256>>>(
        (const float4*)x, (const float4*)Wq, (const float4*)Wk,
        (const float4*)Wv, (const float4*)Wo,
        (uint2*)xh, (uint2*)xl, (uint2*)wqh, (uint2*)wkh,
        (uint2*)wvh, (uint2*)woh);

    // 2) fused QKV projections with rope/split epilogues (one launch)
    proj_qkv_kernel<<<768, 256, GB_SMEM>>>(
        xh, xl, wqh, wkh, wvh, cosb, sinb,
        (uint32_t*)qhp, (uint32_t*)qlp, (uint32_t*)khp, (uint32_t*)vhp);

    // 3) attention
    attn_mma_kernel<<<dim3(16, 32, 2), 256, A_SMEM>>>(
        (const uint32_t*)qhp, (const uint32_t*)qlp,
        (const uint32_t*)khp, (const uint32_t*)vhp,
        (uint32_t*)ahp, (uint32_t*)alp);

    // 4) output projection
    gemm_out_kernel<<<dim3(16, 32), 256, GB_SMEM>>>(ahp, alp, woh, out);
}

// round 13
// speedup vs baseline: 1.1700x; 1.0747x over previous
#include <cuda_runtime.h>
#include <cuda_fp16.h>
#include <cstdint>
#include <math.h>

// Problem constants
constexpr int Bb  = 2;
constexpr int Ss  = 2048;
constexpr int Ee  = 2048;
constexpr int Hh  = 32;
constexpr int HKVv= 8;
constexpr int Dd  = 64;
constexpr int MS  = Bb * Ss;      // 4096 rows

// ---------------------------------------------------------------------------
// Scratch. fp16 pairs packed in uint32 (low half = even element).
// ---------------------------------------------------------------------------
__device__ uint32_t s_xh[MS * Ee / 2],  s_xl[MS * Ee / 2];
__device__ uint32_t s_wqh[Ee * Ee / 2];
__device__ uint32_t s_wkh[512 * Ee / 2];
__device__ uint32_t s_wvh[512 * Ee / 2];
__device__ uint32_t s_woh[Ee * Ee / 2];
__device__ uint32_t s_qh[MS * 1024];
__device__ uint32_t s_kh[MS * 256];
__device__ uint32_t s_vh[MS * 256];
__device__ uint32_t s_ah[MS * 1024], s_al[MS * 1024];

// ---------------------------------------------------------------------------
// Helpers
// ---------------------------------------------------------------------------
__device__ __forceinline__ uint32_t smem_u32(const void* p) {
    uint32_t a;
    asm("{ .reg .u64 t; cvta.to.shared.u64 t, %1; cvt.u32.u64 %0, t; }" : "=r"(a) : "l"(p));
    return a;
}

#define LDX4(r0, r1, r2, r3, addr) \
    asm volatile("ldmatrix.sync.aligned.m8n8.x4.shared.b16 {%0,%1,%2,%3}, [%4];" \
        : "=r"(r0), "=r"(r1), "=r"(r2), "=r"(r3) : "r"(addr))

#define LDX4T(r0, r1, r2, r3, addr) \
    asm volatile("ldmatrix.sync.aligned.m8n8.x4.trans.shared.b16 {%0,%1,%2,%3}, [%4];" \
        : "=r"(r0), "=r"(r1), "=r"(r2), "=r"(r3) : "r"(addr))

#define CP_ASYNC16(dst, src) \
    asm volatile("cp.async.cg.shared.global [%0], [%1], 16;" :: "r"(dst), "l"(src))
#define CP_COMMIT() asm volatile("cp.async.commit_group;")
#define CP_WAIT(n)  asm volatile("cp.async.wait_group %0;" :: "n"(n))

__device__ __forceinline__ void mma_f16(float c[4], const uint32_t a[4], const uint32_t b[2]) {
    asm volatile("mma.sync.aligned.m16n8k16.row.col.f32.f16.f16.f32 "
                 "{%0,%1,%2,%3}, {%4,%5,%6,%7}, {%8,%9}, {%0,%1,%2,%3};"
                 : "+f"(c[0]), "+f"(c[1]), "+f"(c[2]), "+f"(c[3])
                 : "r"(a[0]), "r"(a[1]), "r"(a[2]), "r"(a[3]), "r"(b[0]), "r"(b[1]));
}

__device__ __forceinline__ uint32_t packf(float x0, float x1) {
    __half2 h = __floats2half2_rn(x0, x1);
    return *reinterpret_cast<uint32_t*>(&h);
}
__device__ __forceinline__ uint32_t packlo(uint32_t ph, float x0, float x1) {
    __half2 h = *reinterpret_cast<__half2*>(&ph);
    return packf(x0 - __low2float(h), x1 - __high2float(h));
}

// ---------------------------------------------------------------------------
// Fused split kernel: x -> hi+lo; weights -> hi. One launch.
// ---------------------------------------------------------------------------
constexpr int N4_X  = MS * Ee / 4;
constexpr int N4_WQ = Ee * Ee / 4;
constexpr int N4_WK = 512 * Ee / 4;
constexpr int N4_TOT = N4_X + N4_WQ + 2 * N4_WK + N4_WQ;

__global__ void split_all_kernel(
    const float4* __restrict__ x,  const float4* __restrict__ wq,
    const float4* __restrict__ wk, const float4* __restrict__ wv,
    const float4* __restrict__ wo,
    uint2* __restrict__ xh,  uint2* __restrict__ xl,
    uint2* __restrict__ wqh, uint2* __restrict__ wkh,
    uint2* __restrict__ wvh, uint2* __restrict__ woh)
{
    int i = blockIdx.x * blockDim.x + threadIdx.x;
    if (i >= N4_TOT) return;
    const float4* src; uint2* hi; uint2* lo = nullptr; int j = i;
    if (j < N4_X)                   { src = x;  hi = xh;  lo = xl; }
    else if ((j -= N4_X)  < N4_WQ)  { src = wq; hi = wqh; }
    else if ((j -= N4_WQ) < N4_WK)  { src = wk; hi = wkh; }
    else if ((j -= N4_WK) < N4_WK)  { src = wv; hi = wvh; }
    else { j -= N4_WK;                src = wo; hi = woh; }
    float4 f = src[j];
    uint32_t h0 = packf(f.x, f.y), h1 = packf(f.z, f.w);
    hi[j] = make_uint2(h0, h1);
    if (lo) lo[j] = make_uint2(packlo(h0, f.x, f.y), packlo(h1, f.z, f.w));
}

// ---------------------------------------------------------------------------
// fp16 2-term GEMM mainloop (R10/R12 config): warp tile 32x64, BK=32, 4-stage
// cp.async, 2 CTAs/SM, single sync per stage. smem rows 64B, XOR swizzle.
// ---------------------------------------------------------------------------
constexpr int GB_TILE  = 128 * 64;         // 8192
constexpr int GB_STAGE = 3 * GB_TILE;      // 24576 (Ah, Al, Bh)
constexpr int GB_SMEM  = 4 * GB_STAGE;     // 98304; 2 CTAs/SM

__device__ __forceinline__ uint32_t swz(uint32_t row, uint32_t chunk) {
    return row * 64 + ((chunk ^ ((row >> 1) & 3)) << 4);
}

__device__ __forceinline__ void gemm_mainloop(
    const char* Ah, const char* Al, const char* Bh,
    int m0, int n0, char* smem, float acc[2][8][4])
{
    const uint32_t sbase = smem_u32(smem);
    const int tid  = threadIdx.x;
    const int wid  = tid >> 5;
    const int lane = tid & 31;
    const int wm = wid & 3;        // 4 m-groups of 32
    const int wn = wid >> 2;       // 2 n-groups of 64
    const int lmrow = lane & 15;
    const int lmc   = lane >> 4;

#pragma unroll
    for (int i = 0; i < 2; ++i)
#pragma unroll
        for (int j = 0; j < 8; ++j)
#pragma unroll
            for (int r = 0; r < 4; ++r) acc[i][j][r] = 0.f;

    auto issue = [&](int kt, int s) {
#pragma unroll
        for (int c = 0; c < 6; ++c) {
            int ch  = c * 256 + tid;
            int arr = ch >> 9;          // 0=Ah 1=Al 2=Bh
            int r   = (ch >> 2) & 127;
            int c16 = ch & 3;
            const char* g;
            if      (arr == 0) g = Ah + (size_t)(m0 + r) * 4096 + kt * 64 + c16 * 16;
            else if (arr == 1) g = Al + (size_t)(m0 + r) * 4096 + kt * 64 + c16 * 16;
            else               g = Bh + (size_t)(n0 + r) * 4096 + kt * 64 + c16 * 16;
            uint32_t dst = sbase + s * GB_STAGE + arr * GB_TILE + swz(r, c16);
            CP_ASYNC16(dst, g);
        }
        CP_COMMIT();
    };

    issue(0, 0);
    issue(1, 1);
    issue(2, 2);

    constexpr int NT = 64;
    for (int kt = 0; kt < NT; ++kt) {
        const int s = kt & 3;
        if (kt + 2 < NT)      { CP_WAIT(2); }
        else if (kt + 1 < NT) { CP_WAIT(1); }
        else                  { CP_WAIT(0); }
        __syncthreads();
        if (kt + 3 < NT) issue(kt + 3, (kt + 3) & 3);

        const uint32_t tb = sbase + s * GB_STAGE;
#pragma unroll
        for (int ks = 0; ks < 2; ++ks) {
            const uint32_t kchunk = ks * 2 + lmc;
            uint32_t bh[8][2];
#pragma unroll
            for (int g16 = 0; g16 < 4; ++g16) {
                uint32_t r0, r1, r2, r3;
                LDX4(r0, r1, r2, r3,
                     tb + 2 * GB_TILE + swz(wn * 64 + g16 * 16 + lmrow, kchunk));
                bh[g16 * 2][0] = r0; bh[g16 * 2][1] = r2;
                bh[g16 * 2 + 1][0] = r1; bh[g16 * 2 + 1][1] = r3;
            }
            uint32_t afh[2][4], afl[2][4];
#pragma unroll
            for (int mt = 0; mt < 2; ++mt) {
                LDX4(afh[mt][0], afh[mt][1], afh[mt][2], afh[mt][3],
                     tb + swz(wm * 32 + mt * 16 + lmrow, kchunk));
                LDX4(afl[mt][0], afl[mt][1], afl[mt][2], afl[mt][3],
                     tb + GB_TILE + swz(wm * 32 + mt * 16 + lmrow, kchunk));
            }
#pragma unroll
            for (int mt = 0; mt < 2; ++mt)
#pragma unroll
                for (int nt = 0; nt < 8; ++nt) {
                    mma_f16(acc[mt][nt], afh[mt], bh[nt]);
                    mma_f16(acc[mt][nt], afl[mt], bh[nt]);
                }
        }
    }
}

// ---------------------------------------------------------------------------
// Fused QKV projection: one launch, 768 CTAs. Q epilogue folds the 0.125
// softmax scale and writes fp16 hi only (single-term QK).
// ---------------------------------------------------------------------------
__global__ void __launch_bounds__(256, 2) proj_qkv_kernel(
    const void* xh_, const void* xl_,
    const void* wqh_, const void* wkh_, const void* wvh_,
    const float* __restrict__ cosb, const float* __restrict__ sinb,
    uint32_t* __restrict__ qh,
    uint32_t* __restrict__ kh, uint32_t* __restrict__ vh)
{
    extern __shared__ char smem[];
    const char* xh = (const char*)xh_;
    const char* xl = (const char*)xl_;
    const int id = blockIdx.x;
    const int tid  = threadIdx.x;
    const int wid  = tid >> 5;
    const int lane = tid & 31;
    const int wm = wid & 3;
    const int wn = wid >> 2;
    const int g  = lane >> 2;
    const int tq = lane & 3;

    float acc[2][8][4];

    if (id < 512) {
        // ---- Q projection (scaled by 0.125, hi only) ----
        const int m0 = (id >> 4) * 128;
        const int n0 = (id & 15) * 128;
        gemm_mainloop(xh, xl, (const char*)wqh_, m0, n0, smem, acc);
        const int head = (n0 + wn * 64) >> 6;
#pragma unroll
        for (int mt = 0; mt < 2; ++mt) {
#pragma unroll
            for (int rr = 0; rr < 2; ++rr) {
                int row = m0 + wm * 32 + mt * 16 + g + rr * 8;
                int s = row & (Ss - 1);
                const float* cb  = cosb + s * 64;
                const float* sb2 = sinb + s * 64;
                uint32_t* qh_p = qh + (size_t)row * 1024 + head * 32;
#pragma unroll
                for (int nt = 0; nt < 4; ++nt) {
                    int d = nt * 8 + tq * 2;
                    float2 c1 = *(const float2*)(cb + d);
                    float2 s1 = *(const float2*)(sb2 + d);
                    float2 c2 = *(const float2*)(cb + d + 32);
                    float2 s2 = *(const float2*)(sb2 + d + 32);
                    float x10 = acc[mt][nt][rr * 2],     x11 = acc[mt][nt][rr * 2 + 1];
                    float x20 = acc[mt][nt + 4][rr * 2], x21 = acc[mt][nt + 4][rr * 2 + 1];
                    float y0 = (x10 * c1.x - x20 * s1.x) * 0.125f;
                    float y1 = (x11 * c1.y - x21 * s1.y) * 0.125f;
                    float y2 = (x20 * c2.x + x10 * s2.x) * 0.125f;
                    float y3 = (x21 * c2.y + x11 * s2.y) * 0.125f;
                    qh_p[nt * 4 + tq]      = packf(y0, y1);
                    qh_p[16 + nt * 4 + tq] = packf(y2, y3);
                }
            }
        }
    } else if (id < 640) {
        // ---- K projection ----
        const int id2 = id - 512;
        const int m0 = (id2 >> 2) * 128;
        const int n0 = (id2 & 3) * 128;
        gemm_mainloop(xh, xl, (const char*)wkh_, m0, n0, smem, acc);
        const int head = (n0 + wn * 64) >> 6;
#pragma unroll
        for (int mt = 0; mt < 2; ++mt) {
#pragma unroll
            for (int rr = 0; rr < 2; ++rr) {
                int row = m0 + wm * 32 + mt * 16 + g + rr * 8;
                int s = row & (Ss - 1);
                const float* cb  = cosb + s * 64;
                const float* sb2 = sinb + s * 64;
                uint32_t* kh_p = kh + (size_t)row * 256 + head * 32;
#pragma unroll
                for (int nt = 0; nt < 4; ++nt) {
                    int d = nt * 8 + tq * 2;
                    float2 c1 = *(const float2*)(cb + d);
                    float2 s1 = *(const float2*)(sb2 + d);
                    float2 c2 = *(const float2*)(cb + d + 32);
                    float2 s2 = *(const float2*)(sb2 + d + 32);
                    float x10 = acc[mt][nt][rr * 2],     x11 = acc[mt][nt][rr * 2 + 1];
                    float x20 = acc[mt][nt + 4][rr * 2], x21 = acc[mt][nt + 4][rr * 2 + 1];
                    float y0 = x10 * c1.x - x20 * s1.x;
                    float y1 = x11 * c1.y - x21 * s1.y;
                    float y2 = x20 * c2.x + x10 * s2.x;
                    float y3 = x21 * c2.y + x11 * s2.y;
                    kh_p[nt * 4 + tq]      = packf(y0, y1);
                    kh_p[16 + nt * 4 + tq] = packf(y2, y3);
                }
            }
        }
    } else {
        // ---- V projection ----
        const int id2 = id - 640;
        const int m0 = (id2 >> 2) * 128;
        const int n0 = (id2 & 3) * 128;
        gemm_mainloop(xh, xl, (const char*)wvh_, m0, n0, smem, acc);
        const int cp0 = (n0 + wn * 64) >> 1;
#pragma unroll
        for (int mt = 0; mt < 2; ++mt) {
#pragma unroll
            for (int rr = 0; rr < 2; ++rr) {
                int row = m0 + wm * 32 + mt * 16 + g + rr * 8;
                uint32_t* vh_p = vh + (size_t)row * 256 + cp0;
#pragma unroll
                for (int nt = 0; nt < 8; ++nt)
                    vh_p[nt * 4 + tq] = packf(acc[mt][nt][rr * 2], acc[mt][nt][rr * 2 + 1]);
            }
        }
    }
}

// ---------------------------------------------------------------------------
// O projection: fp32 output to d_out.
// ---------------------------------------------------------------------------
__global__ void __launch_bounds__(256, 2) gemm_out_kernel(
    const void* Ah, const void* Al, const void* Bh, float* C)
{
    extern __shared__ char smem[];
    const int tid  = threadIdx.x;
    const int wid  = tid >> 5;
    const int lane = tid & 31;
    const int m0 = blockIdx.y * 128;
    const int n0 = blockIdx.x * 128;
    const int wm = wid & 3;
    const int wn = wid >> 2;
    float acc[2][8][4];
    gemm_mainloop((const char*)Ah, (const char*)Al, (const char*)Bh, m0, n0, smem, acc);
    const int g = lane >> 2;
    const int t = lane & 3;
#pragma unroll
    for (int mt = 0; mt < 2; ++mt) {
#pragma unroll
        for (int nt = 0; nt < 8; ++nt) {
            int r = m0 + wm * 32 + mt * 16 + g;
            int c = n0 + wn * 64 + nt * 8 + t * 2;
            *(float2*)(C + (size_t)r * 2048 + c)       = make_float2(acc[mt][nt][0], acc[mt][nt][1]);
            *(float2*)(C + (size_t)(r + 8) * 2048 + c) = make_float2(acc[mt][nt][2], acc[mt][nt][3]);
        }
    }
}

// ---------------------------------------------------------------------------
// Flash attention. QK: single-term Qh*Kh (Q pre-scaled). PV: single-term Ph*Vh.
// 3-stage KV cp.async, single sync per tile.
// ---------------------------------------------------------------------------
constexpr int AROW   = 144;
constexpr int A_QH   = 0;
constexpr int A_KV0  = A_QH + 128 * AROW;      // 18432
constexpr int KV_ARR = 64 * AROW;              // 9216 (KH, VH)
constexpr int KVSTAGE = 2 * KV_ARR;            // 18432
constexpr int A_SMEM  = A_KV0 + 3 * KVSTAGE;   // 73728

__global__ void __launch_bounds__(256, 1) attn_mma_kernel(
    const uint32_t* __restrict__ qh_g,
    const uint32_t* __restrict__ kh_g, const uint32_t* __restrict__ vh_g,
    uint32_t* __restrict__ ah_g, uint32_t* __restrict__ al_g)
{
    extern __shared__ char sm[];
    const uint32_t sb = smem_u32(sm);
    const int tid  = threadIdx.x;
    const int wid  = tid >> 5;
    const int lane = tid & 31;
    const int q0 = blockIdx.x * 128;
    const int h  = blockIdx.y;
    const int b  = blockIdx.z;
    const int hkv = h >> 2;

    const int lmrow  = lane & 15;
    const int lmk    = (lane >> 4) * 16;

    auto issue_kv = [&](int t, int s) {
#pragma unroll
        for (int c = 0; c < 4; ++c) {
            int ch  = c * 256 + tid;
            int arr = ch >> 9;
            int r   = (ch >> 3) & 63;
            int c16 = ch & 7;
            const uint32_t* gsrc = arr ? vh_g : kh_g;
            const char* g = (const char*)gsrc
                + ((size_t)(b * Ss + t * 64 + r) * 256 + hkv * 32) * 4 + c16 * 16;
            uint32_t dst = sb + A_KV0 + s * KVSTAGE + arr * KV_ARR + r * AROW + c16 * 16;
            CP_ASYNC16(dst, g);
        }
        CP_COMMIT();
    };

    issue_kv(0, 0);
    issue_kv(1, 1);

    // stage Q hi only: 1024 chunks, 4 per thread
#pragma unroll
    for (int c = 0; c < 4; ++c) {
        int ch  = c * 256 + tid;
        int r   = ch >> 3;
        int c16 = ch & 7;
        const char* src = (const char*)qh_g
            + ((size_t)(b * Ss + q0 + r) * 1024 + h * 32) * 4 + c16 * 16;
        *(uint4*)(sm + A_QH + r * AROW + c16 * 16) = *(const uint4*)src;
    }
    __syncthreads();

    uint32_t qfh[4][4];
#pragma unroll
    for (int kd = 0; kd < 4; ++kd) {
        LDX4(qfh[kd][0], qfh[kd][1], qfh[kd][2], qfh[kd][3],
             sb + A_QH + (uint32_t)(wid * 16 + lmrow) * AROW + kd * 32 + lmk);
    }

    float o[8][4];
#pragma unroll
    for (int j = 0; j < 8; ++j)
#pragma unroll
        for (int r = 0; r < 4; ++r) o[j][r] = 0.f;
    float mstat[2] = {-1e30f, -1e30f};
    float lstat[2] = {0.f, 0.f};

    constexpr int NTT = Ss / 64;   // 32
    int s3 = 0;
    for (int t = 0; t < NTT; ++t) {
        if (t + 1 < NTT) { CP_WAIT(1); } else { CP_WAIT(0); }
        __syncthreads();
        if (t + 2 < NTT) {
            int sn = s3 + 2; if (sn >= 3) sn -= 3;
            issue_kv(t + 2, sn);
        }

        const uint32_t kvb = sb + A_KV0 + s3 * KVSTAGE;

        // ---- S = Q K^T (single-term, pre-scaled) ----
        float sreg[8][4];
#pragma unroll
        for (int j = 0; j < 8; ++j)
#pragma unroll
            for (int r = 0; r < 4; ++r) sreg[j][r] = 0.f;

#pragma unroll
        for (int kd = 0; kd < 4; ++kd) {
#pragma unroll
            for (int j16 = 0; j16 < 4; ++j16) {
                uint32_t h0, h1, h2, h3;
                LDX4(h0, h1, h2, h3,
                     kvb + (uint32_t)(j16 * 16 + lmrow) * AROW + kd * 32 + lmk);
                uint32_t bh0[2] = {h0, h2}, bh1[2] = {h1, h3};
                mma_f16(sreg[2 * j16],     qfh[kd], bh0);
                mma_f16(sreg[2 * j16 + 1], qfh[kd], bh1);
            }
        }

        // ---- online softmax (scores already scaled) ----
#pragma unroll
        for (int hf = 0; hf < 2; ++hf) {
            float mx = -1e30f;
#pragma unroll
            for (int j = 0; j < 8; ++j)
                mx = fmaxf(mx, fmaxf(sreg[j][hf * 2], sreg[j][hf * 2 + 1]));
            mx = fmaxf(mx, __shfl_xor_sync(0xffffffffu, mx, 1));
            mx = fmaxf(mx, __shfl_xor_sync(0xffffffffu, mx, 2));
            float mnew = fmaxf(mstat[hf], mx);
            float corr = __expf(mstat[hf] - mnew);
            float sum = 0.f;
#pragma unroll
            for (int j = 0; j < 8; ++j) {
                sreg[j][hf * 2]     = __expf(sreg[j][hf * 2] - mnew);
                sreg[j][hf * 2 + 1] = __expf(sreg[j][hf * 2 + 1] - mnew);
                sum += sreg[j][hf * 2] + sreg[j][hf * 2 + 1];
            }
            sum += __shfl_xor_sync(0xffffffffu, sum, 1);
            sum += __shfl_xor_sync(0xffffffffu, sum, 2);
            lstat[hf] = lstat[hf] * corr + sum;
            mstat[hf] = mnew;
#pragma unroll
            for (int j = 0; j < 8; ++j) {
                o[j][hf * 2]     *= corr;
                o[j][hf * 2 + 1] *= corr;
            }
        }

        // ---- O += P V (single-term Ph*Vh) ----
#pragma unroll
        for (int kk = 0; kk < 4; ++kk) {
            uint32_t ah[4];
            ah[0] = packf(sreg[2 * kk][0],     sreg[2 * kk][1]);
            ah[1] = packf(sreg[2 * kk][2],     sreg[2 * kk][3]);
            ah[2] = packf(sreg[2 * kk + 1][0], sreg[2 * kk + 1][1]);
            ah[3] = packf(sreg[2 * kk + 1][2], sreg[2 * kk + 1][3]);
#pragma unroll
            for (int j = 0; j < 4; ++j) {
                uint32_t vh0, vh1, vh2, vh3;
                LDX4T(vh0, vh1, vh2, vh3,
                      kvb + KV_ARR + (uint32_t)(kk * 16 + lmrow) * AROW + j * 32 + lmk);
                uint32_t bh0[2] = {vh0, vh1}, bh1[2] = {vh2, vh3};
                mma_f16(o[2 * j],     ah, bh0);
                mma_f16(o[2 * j + 1], ah, bh1);
            }
        }
        if (++s3 == 3) s3 = 0;
    }

    const int g  = lane >> 2;
    const int tt = lane & 3;
    const float inv0 = 1.f / lstat[0];
    const float inv1 = 1.f / lstat[1];
    const int mrow = q0 + wid * 16 + g;
    uint32_t* ah0 = ah_g + (size_t)(b * Ss + mrow) * 1024 + h * 32;
    uint32_t* al0 = al_g + (size_t)(b * Ss + mrow) * 1024 + h * 32;
    uint32_t* ah1 = ah0 + (size_t)8 * 1024;
    uint32_t* al1 = al0 + (size_t)8 * 1024;
#pragma unroll
    for (int j = 0; j < 8; ++j) {
        float y0 = o[j][0] * inv0, y1 = o[j][1] * inv0;
        uint32_t ph = packf(y0, y1);
        ah0[j * 4 + tt] = ph;
        al0[j * 4 + tt] = packlo(ph, y0, y1);
        float y2 = o[j][2] * inv1, y3 = o[j][3] * inv1;
        uint32_t ph2 = packf(y2, y3);
        ah1[j * 4 + tt] = ph2;
        al1[j * 4 + tt] = packlo(ph2, y2, y3);
    }
}

// ---------------------------------------------------------------------------
extern "C" void kernel_launch(void* const* d_in, const int* in_sizes, int n_in,
                              void* d_out, int out_size)
{
    (void)in_sizes; (void)n_in; (void)out_size;
    const float* x    = (const float*)d_in[0];
    const float* cosb = (const float*)d_in[1];
    const float* sinb = (const float*)d_in[2];
    const float* Wq   = (const float*)d_in[3];
    const float* Wk   = (const float*)d_in[4];
    const float* Wv   = (const float*)d_in[5];
    const float* Wo   = (const float*)d_in[6];
    float* out = (float*)d_out;

    void *xh, *xl, *wqh, *wkh, *wvh, *woh;
    void *qhp, *khp, *vhp, *ahp, *alp;
    cudaGetSymbolAddress(&xh, s_xh);   cudaGetSymbolAddress(&xl, s_xl);
    cudaGetSymbolAddress(&wqh, s_wqh); cudaGetSymbolAddress(&wkh, s_wkh);
    cudaGetSymbolAddress(&wvh, s_wvh); cudaGetSymbolAddress(&woh, s_woh);
    cudaGetSymbolAddress(&qhp, s_qh);
    cudaGetSymbolAddress(&khp, s_kh);  cudaGetSymbolAddress(&vhp, s_vh);
    cudaGetSymbolAddress(&ahp, s_ah);  cudaGetSymbolAddress(&alp, s_al);

    cudaFuncSetAttribute(proj_qkv_kernel, cudaFuncAttributeMaxDynamicSharedMemorySize, GB_SMEM);
    cudaFuncSetAttribute(gemm_out_kernel, cudaFuncAttributeMaxDynamicSharedMemorySize, GB_SMEM);
    cudaFuncSetAttribute(attn_mma_kernel, cudaFuncAttributeMaxDynamicSharedMemorySize, A_SMEM);

    // 1) pre-split x (hi+lo) and weights (hi)
    split_all_kernel<<<(N4_TOT + 255) / 256, 256>>>(
        (const float4*)x, (const float4*)Wq, (const float4*)Wk,
        (const float4*)Wv, (const float4*)Wo,
        (uint2*)xh, (uint2*)xl, (uint2*)wqh, (uint2*)wkh,
        (uint2*)wvh, (uint2*)woh);

    // 2) fused QKV projections with rope/split epilogues (one launch)
    proj_qkv_kernel<<<768, 256, GB_SMEM>>>(
        xh, xl, wqh, wkh, wvh, cosb, sinb,
        (uint32_t*)qhp, (uint32_t*)khp, (uint32_t*)vhp);

    // 3) attention
    attn_mma_kernel<<<dim3(16, 32, 2), 256, A_SMEM>>>(
        (const uint32_t*)qhp, (const uint32_t*)khp, (const uint32_t*)vhp,
        (uint32_t*)ahp, (uint32_t*)alp);

    // 4) output projection
    gemm_out_kernel<<<dim3(16, 32), 256, GB_SMEM>>>(ahp, alp, woh, out);
}

// round 14
// speedup vs baseline: 1.3379x; 1.1435x over previous
#include <cuda_runtime.h>
#include <cuda_fp16.h>
#include <cstdint>
#include <math.h>

// Problem constants
constexpr int Bb  = 2;
constexpr int Ss  = 2048;
constexpr int Ee  = 2048;
constexpr int Hh  = 32;
constexpr int HKVv= 8;
constexpr int Dd  = 64;
constexpr int MS  = Bb * Ss;      // 4096 rows

// ---------------------------------------------------------------------------
// Scratch. fp16 pairs packed in uint32 (low half = even element).
// ---------------------------------------------------------------------------
__device__ uint32_t s_xh[MS * Ee / 2],  s_xl[MS * Ee / 2];
__device__ uint32_t s_wqh[Ee * Ee / 2];
__device__ uint32_t s_wkh[512 * Ee / 2];
__device__ uint32_t s_wvh[512 * Ee / 2];
__device__ uint32_t s_woh[Ee * Ee / 2];
__device__ uint32_t s_qh[MS * 1024];
__device__ uint32_t s_kh[MS * 256];
__device__ uint32_t s_vh[MS * 256];
__device__ uint32_t s_ah[MS * 1024];

// ---------------------------------------------------------------------------
// Helpers
// ---------------------------------------------------------------------------
__device__ __forceinline__ uint32_t smem_u32(const void* p) {
    uint32_t a;
    asm("{ .reg .u64 t; cvta.to.shared.u64 t, %1; cvt.u32.u64 %0, t; }" : "=r"(a) : "l"(p));
    return a;
}

#define LDX4(r0, r1, r2, r3, addr) \
    asm volatile("ldmatrix.sync.aligned.m8n8.x4.shared.b16 {%0,%1,%2,%3}, [%4];" \
        : "=r"(r0), "=r"(r1), "=r"(r2), "=r"(r3) : "r"(addr))

#define LDX4T(r0, r1, r2, r3, addr) \
    asm volatile("ldmatrix.sync.aligned.m8n8.x4.trans.shared.b16 {%0,%1,%2,%3}, [%4];" \
        : "=r"(r0), "=r"(r1), "=r"(r2), "=r"(r3) : "r"(addr))

#define CP_ASYNC16(dst, src) \
    asm volatile("cp.async.cg.shared.global [%0], [%1], 16;" :: "r"(dst), "l"(src))
#define CP_COMMIT() asm volatile("cp.async.commit_group;")
#define CP_WAIT(n)  asm volatile("cp.async.wait_group %0;" :: "n"(n))

__device__ __forceinline__ void mma_f16(float c[4], const uint32_t a[4], const uint32_t b[2]) {
    asm volatile("mma.sync.aligned.m16n8k16.row.col.f32.f16.f16.f32 "
                 "{%0,%1,%2,%3}, {%4,%5,%6,%7}, {%8,%9}, {%0,%1,%2,%3};"
                 : "+f"(c[0]), "+f"(c[1]), "+f"(c[2]), "+f"(c[3])
                 : "r"(a[0]), "r"(a[1]), "r"(a[2]), "r"(a[3]), "r"(b[0]), "r"(b[1]));
}

__device__ __forceinline__ uint32_t packf(float x0, float x1) {
    __half2 h = __floats2half2_rn(x0, x1);
    return *reinterpret_cast<uint32_t*>(&h);
}
__device__ __forceinline__ uint32_t packlo(uint32_t ph, float x0, float x1) {
    __half2 h = *reinterpret_cast<__half2*>(&ph);
    return packf(x0 - __low2float(h), x1 - __high2float(h));
}

// ---------------------------------------------------------------------------
// Fused split kernel: x -> hi+lo; weights -> hi. One launch.
// ---------------------------------------------------------------------------
constexpr int N4_X  = MS * Ee / 4;
constexpr int N4_WQ = Ee * Ee / 4;
constexpr int N4_WK = 512 * Ee / 4;
constexpr int N4_TOT = N4_X + N4_WQ + 2 * N4_WK + N4_WQ;

__global__ void split_all_kernel(
    const float4* __restrict__ x,  const float4* __restrict__ wq,
    const float4* __restrict__ wk, const float4* __restrict__ wv,
    const float4* __restrict__ wo,
    uint2* __restrict__ xh,  uint2* __restrict__ xl,
    uint2* __restrict__ wqh, uint2* __restrict__ wkh,
    uint2* __restrict__ wvh, uint2* __restrict__ woh)
{
    int i = blockIdx.x * blockDim.x + threadIdx.x;
    if (i >= N4_TOT) return;
    const float4* src; uint2* hi; uint2* lo = nullptr; int j = i;
    if (j < N4_X)                   { src = x;  hi = xh;  lo = xl; }
    else if ((j -= N4_X)  < N4_WQ)  { src = wq; hi = wqh; }
    else if ((j -= N4_WQ) < N4_WK)  { src = wk; hi = wkh; }
    else if ((j -= N4_WK) < N4_WK)  { src = wv; hi = wvh; }
    else { j -= N4_WK;                src = wo; hi = woh; }
    float4 f = src[j];
    uint32_t h0 = packf(f.x, f.y), h1 = packf(f.z, f.w);
    hi[j] = make_uint2(h0, h1);
    if (lo) lo[j] = make_uint2(packlo(h0, f.x, f.y), packlo(h1, f.z, f.w));
}

// ---------------------------------------------------------------------------
// fp16 2-term GEMM mainloop (QKV projections): warp tile 32x64, BK=32,
// 4-stage cp.async, 2 CTAs/SM, single sync per stage. 64B rows, XOR swizzle.
// ---------------------------------------------------------------------------
constexpr int GB_TILE  = 128 * 64;         // 8192
constexpr int GB_STAGE = 3 * GB_TILE;      // 24576 (Ah, Al, Bh)
constexpr int GB_SMEM  = 4 * GB_STAGE;     // 98304; 2 CTAs/SM

__device__ __forceinline__ uint32_t swz(uint32_t row, uint32_t chunk) {
    return row * 64 + ((chunk ^ ((row >> 1) & 3)) << 4);
}

__device__ __forceinline__ void gemm_mainloop(
    const char* Ah, const char* Al, const char* Bh,
    int m0, int n0, char* smem, float acc[2][8][4])
{
    const uint32_t sbase = smem_u32(smem);
    const int tid  = threadIdx.x;
    const int wid  = tid >> 5;
    const int lane = tid & 31;
    const int wm = wid & 3;
    const int wn = wid >> 2;
    const int lmrow = lane & 15;
    const int lmc   = lane >> 4;

#pragma unroll
    for (int i = 0; i < 2; ++i)
#pragma unroll
        for (int j = 0; j < 8; ++j)
#pragma unroll
            for (int r = 0; r < 4; ++r) acc[i][j][r] = 0.f;

    auto issue = [&](int kt, int s) {
#pragma unroll
        for (int c = 0; c < 6; ++c) {
            int ch  = c * 256 + tid;
            int arr = ch >> 9;          // 0=Ah 1=Al 2=Bh
            int r   = (ch >> 2) & 127;
            int c16 = ch & 3;
            const char* g;
            if      (arr == 0) g = Ah + (size_t)(m0 + r) * 4096 + kt * 64 + c16 * 16;
            else if (arr == 1) g = Al + (size_t)(m0 + r) * 4096 + kt * 64 + c16 * 16;
            else               g = Bh + (size_t)(n0 + r) * 4096 + kt * 64 + c16 * 16;
            uint32_t dst = sbase + s * GB_STAGE + arr * GB_TILE + swz(r, c16);
            CP_ASYNC16(dst, g);
        }
        CP_COMMIT();
    };

    issue(0, 0);
    issue(1, 1);
    issue(2, 2);

    constexpr int NT = 64;
    for (int kt = 0; kt < NT; ++kt) {
        const int s = kt & 3;
        if (kt + 2 < NT)      { CP_WAIT(2); }
        else if (kt + 1 < NT) { CP_WAIT(1); }
        else                  { CP_WAIT(0); }
        __syncthreads();
        if (kt + 3 < NT) issue(kt + 3, (kt + 3) & 3);

        const uint32_t tb = sbase + s * GB_STAGE;
#pragma unroll
        for (int ks = 0; ks < 2; ++ks) {
            const uint32_t kchunk = ks * 2 + lmc;
            uint32_t bh[8][2];
#pragma unroll
            for (int g16 = 0; g16 < 4; ++g16) {
                uint32_t r0, r1, r2, r3;
                LDX4(r0, r1, r2, r3,
                     tb + 2 * GB_TILE + swz(wn * 64 + g16 * 16 + lmrow, kchunk));
                bh[g16 * 2][0] = r0; bh[g16 * 2][1] = r2;
                bh[g16 * 2 + 1][0] = r1; bh[g16 * 2 + 1][1] = r3;
            }
            uint32_t afh[2][4], afl[2][4];
#pragma unroll
            for (int mt = 0; mt < 2; ++mt) {
                LDX4(afh[mt][0], afh[mt][1], afh[mt][2], afh[mt][3],
                     tb + swz(wm * 32 + mt * 16 + lmrow, kchunk));
                LDX4(afl[mt][0], afl[mt][1], afl[mt][2], afl[mt][3],
                     tb + GB_TILE + swz(wm * 32 + mt * 16 + lmrow, kchunk));
            }
#pragma unroll
            for (int mt = 0; mt < 2; ++mt)
#pragma unroll
                for (int nt = 0; nt < 8; ++nt) {
                    mma_f16(acc[mt][nt], afh[mt], bh[nt]);
                    mma_f16(acc[mt][nt], afl[mt], bh[nt]);
                }
        }
    }
}

// ---------------------------------------------------------------------------
// Single-term GEMM mainloop (O projection): A hi only. BK=32, 4-stage,
// 2 CTAs/SM (64 KB smem).
// ---------------------------------------------------------------------------
constexpr int G1_STAGE = 2 * GB_TILE;      // 16384 (Ah, Bh)
constexpr int G1_SMEM  = 4 * G1_STAGE;     // 65536

__device__ __forceinline__ void gemm_mainloop_1t(
    const char* Ah, const char* Bh,
    int m0, int n0, char* smem, float acc[2][8][4])
{
    const uint32_t sbase = smem_u32(smem);
    const int tid  = threadIdx.x;
    const int wid  = tid >> 5;
    const int lane = tid & 31;
    const int wm = wid & 3;
    const int wn = wid >> 2;
    const int lmrow = lane & 15;
    const int lmc   = lane >> 4;

#pragma unroll
    for (int i = 0; i < 2; ++i)
#pragma unroll
        for (int j = 0; j < 8; ++j)
#pragma unroll
            for (int r = 0; r < 4; ++r) acc[i][j][r] = 0.f;

    auto issue = [&](int kt, int s) {
#pragma unroll
        for (int c = 0; c < 4; ++c) {
            int ch  = c * 256 + tid;
            int arr = ch >> 9;          // 0=Ah 1=Bh
            int r   = (ch >> 2) & 127;
            int c16 = ch & 3;
            const char* g = (arr == 0)
                ? Ah + (size_t)(m0 + r) * 4096 + kt * 64 + c16 * 16
                : Bh + (size_t)(n0 + r) * 4096 + kt * 64 + c16 * 16;
            uint32_t dst = sbase + s * G1_STAGE + arr * GB_TILE + swz(r, c16);
            CP_ASYNC16(dst, g);
        }
        CP_COMMIT();
    };

    issue(0, 0);
    issue(1, 1);
    issue(2, 2);

    constexpr int NT = 64;
    for (int kt = 0; kt < NT; ++kt) {
        const int s = kt & 3;
        if (kt + 2 < NT)      { CP_WAIT(2); }
        else if (kt + 1 < NT) { CP_WAIT(1); }
        else                  { CP_WAIT(0); }
        __syncthreads();
        if (kt + 3 < NT) issue(kt + 3, (kt + 3) & 3);

        const uint32_t tb = sbase + s * G1_STAGE;
#pragma unroll
        for (int ks = 0; ks < 2; ++ks) {
            const uint32_t kchunk = ks * 2 + lmc;
            uint32_t bh[8][2];
#pragma unroll
            for (int g16 = 0; g16 < 4; ++g16) {
                uint32_t r0, r1, r2, r3;
                LDX4(r0, r1, r2, r3,
                     tb + GB_TILE + swz(wn * 64 + g16 * 16 + lmrow, kchunk));
                bh[g16 * 2][0] = r0; bh[g16 * 2][1] = r2;
                bh[g16 * 2 + 1][0] = r1; bh[g16 * 2 + 1][1] = r3;
            }
            uint32_t afh[2][4];
#pragma unroll
            for (int mt = 0; mt < 2; ++mt)
                LDX4(afh[mt][0], afh[mt][1], afh[mt][2], afh[mt][3],
                     tb + swz(wm * 32 + mt * 16 + lmrow, kchunk));
#pragma unroll
            for (int mt = 0; mt < 2; ++mt)
#pragma unroll
                for (int nt = 0; nt < 8; ++nt)
                    mma_f16(acc[mt][nt], afh[mt], bh[nt]);
        }
    }
}

// ---------------------------------------------------------------------------
// Fused QKV projection: one launch, 768 CTAs. Q pre-scaled by 0.125, hi only.
// ---------------------------------------------------------------------------
__global__ void __launch_bounds__(256, 2) proj_qkv_kernel(
    const void* xh_, const void* xl_,
    const void* wqh_, const void* wkh_, const void* wvh_,
    const float* __restrict__ cosb, const float* __restrict__ sinb,
    uint32_t* __restrict__ qh,
    uint32_t* __restrict__ kh, uint32_t* __restrict__ vh)
{
    extern __shared__ char smem[];
    const char* xh = (const char*)xh_;
    const char* xl = (const char*)xl_;
    const int id = blockIdx.x;
    const int tid  = threadIdx.x;
    const int wid  = tid >> 5;
    const int lane = tid & 31;
    const int wm = wid & 3;
    const int wn = wid >> 2;
    const int g  = lane >> 2;
    const int tq = lane & 3;

    float acc[2][8][4];

    if (id < 512) {
        const int m0 = (id >> 4) * 128;
        const int n0 = (id & 15) * 128;
        gemm_mainloop(xh, xl, (const char*)wqh_, m0, n0, smem, acc);
        const int head = (n0 + wn * 64) >> 6;
#pragma unroll
        for (int mt = 0; mt < 2; ++mt) {
#pragma unroll
            for (int rr = 0; rr < 2; ++rr) {
                int row = m0 + wm * 32 + mt * 16 + g + rr * 8;
                int s = row & (Ss - 1);
                const float* cb  = cosb + s * 64;
                const float* sb2 = sinb + s * 64;
                uint32_t* qh_p = qh + (size_t)row * 1024 + head * 32;
#pragma unroll
                for (int nt = 0; nt < 4; ++nt) {
                    int d = nt * 8 + tq * 2;
                    float2 c1 = *(const float2*)(cb + d);
                    float2 s1 = *(const float2*)(sb2 + d);
                    float2 c2 = *(const float2*)(cb + d + 32);
                    float2 s2 = *(const float2*)(sb2 + d + 32);
                    float x10 = acc[mt][nt][rr * 2],     x11 = acc[mt][nt][rr * 2 + 1];
                    float x20 = acc[mt][nt + 4][rr * 2], x21 = acc[mt][nt + 4][rr * 2 + 1];
                    float y0 = (x10 * c1.x - x20 * s1.x) * 0.125f;
                    float y1 = (x11 * c1.y - x21 * s1.y) * 0.125f;
                    float y2 = (x20 * c2.x + x10 * s2.x) * 0.125f;
                    float y3 = (x21 * c2.y + x11 * s2.y) * 0.125f;
                    qh_p[nt * 4 + tq]      = packf(y0, y1);
                    qh_p[16 + nt * 4 + tq] = packf(y2, y3);
                }
            }
        }
    } else if (id < 640) {
        const int id2 = id - 512;
        const int m0 = (id2 >> 2) * 128;
        const int n0 = (id2 & 3) * 128;
        gemm_mainloop(xh, xl, (const char*)wkh_, m0, n0, smem, acc);
        const int head = (n0 + wn * 64) >> 6;
#pragma unroll
        for (int mt = 0; mt < 2; ++mt) {
#pragma unroll
            for (int rr = 0; rr < 2; ++rr) {
                int row = m0 + wm * 32 + mt * 16 + g + rr * 8;
                int s = row & (Ss - 1);
                const float* cb  = cosb + s * 64;
                const float* sb2 = sinb + s * 64;
                uint32_t* kh_p = kh + (size_t)row * 256 + head * 32;
#pragma unroll
                for (int nt = 0; nt < 4; ++nt) {
                    int d = nt * 8 + tq * 2;
                    float2 c1 = *(const float2*)(cb + d);
                    float2 s1 = *(const float2*)(sb2 + d);
                    float2 c2 = *(const float2*)(cb + d + 32);
                    float2 s2 = *(const float2*)(sb2 + d + 32);
                    float x10 = acc[mt][nt][rr * 2],     x11 = acc[mt][nt][rr * 2 + 1];
                    float x20 = acc[mt][nt + 4][rr * 2], x21 = acc[mt][nt + 4][rr * 2 + 1];
                    float y0 = x10 * c1.x - x20 * s1.x;
                    float y1 = x11 * c1.y - x21 * s1.y;
                    float y2 = x20 * c2.x + x10 * s2.x;
                    float y3 = x21 * c2.y + x11 * s2.y;
                    kh_p[nt * 4 + tq]      = packf(y0, y1);
                    kh_p[16 + nt * 4 + tq] = packf(y2, y3);
                }
            }
        }
    } else {
        const int id2 = id - 640;
        const int m0 = (id2 >> 2) * 128;
        const int n0 = (id2 & 3) * 128;
        gemm_mainloop(xh, xl, (const char*)wvh_, m0, n0, smem, acc);
        const int cp0 = (n0 + wn * 64) >> 1;
#pragma unroll
        for (int mt = 0; mt < 2; ++mt) {
#pragma unroll
            for (int rr = 0; rr < 2; ++rr) {
                int row = m0 + wm * 32 + mt * 16 + g + rr * 8;
                uint32_t* vh_p = vh + (size_t)row * 256 + cp0;
#pragma unroll
                for (int nt = 0; nt < 8; ++nt)
                    vh_p[nt * 4 + tq] = packf(acc[mt][nt][rr * 2], acc[mt][nt][rr * 2 + 1]);
            }
        }
    }
}

// ---------------------------------------------------------------------------
// O projection (single-term): fp32 output to d_out.
// ---------------------------------------------------------------------------
__global__ void __launch_bounds__(256, 2) gemm_out_kernel(
    const void* Ah, const void* Bh, float* C)
{
    extern __shared__ char smem[];
    const int tid  = threadIdx.x;
    const int wid  = tid >> 5;
    const int lane = tid & 31;
    const int m0 = blockIdx.y * 128;
    const int n0 = blockIdx.x * 128;
    const int wm = wid & 3;
    const int wn = wid >> 2;
    float acc[2][8][4];
    gemm_mainloop_1t((const char*)Ah, (const char*)Bh, m0, n0, smem, acc);
    const int g = lane >> 2;
    const int t = lane & 3;
#pragma unroll
    for (int mt = 0; mt < 2; ++mt) {
#pragma unroll
        for (int nt = 0; nt < 8; ++nt) {
            int r = m0 + wm * 32 + mt * 16 + g;
            int c = n0 + wn * 64 + nt * 8 + t * 2;
            *(float2*)(C + (size_t)r * 2048 + c)       = make_float2(acc[mt][nt][0], acc[mt][nt][1]);
            *(float2*)(C + (size_t)(r + 8) * 2048 + c) = make_float2(acc[mt][nt][2], acc[mt][nt][3]);
        }
    }
}

// ---------------------------------------------------------------------------
// Flash attention. QK: single-term Qh*Kh (Q pre-scaled). PV: single-term.
// Epilogue writes fp16 hi only. 3-stage KV cp.async, single sync per tile.
// ---------------------------------------------------------------------------
constexpr int AROW   = 144;
constexpr int A_QH   = 0;
constexpr int A_KV0  = A_QH + 128 * AROW;      // 18432
constexpr int KV_ARR = 64 * AROW;              // 9216 (KH, VH)
constexpr int KVSTAGE = 2 * KV_ARR;            // 18432
constexpr int A_SMEM  = A_KV0 + 3 * KVSTAGE;   // 73728

__global__ void __launch_bounds__(256, 1) attn_mma_kernel(
    const uint32_t* __restrict__ qh_g,
    const uint32_t* __restrict__ kh_g, const uint32_t* __restrict__ vh_g,
    uint32_t* __restrict__ ah_g)
{
    extern __shared__ char sm[];
    const uint32_t sb = smem_u32(sm);
    const int tid  = threadIdx.x;
    const int wid  = tid >> 5;
    const int lane = tid & 31;
    const int q0 = blockIdx.x * 128;
    const int h  = blockIdx.y;
    const int b  = blockIdx.z;
    const int hkv = h >> 2;

    const int lmrow  = lane & 15;
    const int lmk    = (lane >> 4) * 16;

    auto issue_kv = [&](int t, int s) {
#pragma unroll
        for (int c = 0; c < 4; ++c) {
            int ch  = c * 256 + tid;
            int arr = ch >> 9;
            int r   = (ch >> 3) & 63;
            int c16 = ch & 7;
            const uint32_t* gsrc = arr ? vh_g : kh_g;
            const char* g = (const char*)gsrc
                + ((size_t)(b * Ss + t * 64 + r) * 256 + hkv * 32) * 4 + c16 * 16;
            uint32_t dst = sb + A_KV0 + s * KVSTAGE + arr * KV_ARR + r * AROW + c16 * 16;
            CP_ASYNC16(dst, g);
        }
        CP_COMMIT();
    };

    issue_kv(0, 0);
    issue_kv(1, 1);

#pragma unroll
    for (int c = 0; c < 4; ++c) {
        int ch  = c * 256 + tid;
        int r   = ch >> 3;
        int c16 = ch & 7;
        const char* src = (const char*)qh_g
            + ((size_t)(b * Ss + q0 + r) * 1024 + h * 32) * 4 + c16 * 16;
        *(uint4*)(sm + A_QH + r * AROW + c16 * 16) = *(const uint4*)src;
    }
    __syncthreads();

    uint32_t qfh[4][4];
#pragma unroll
    for (int kd = 0; kd < 4; ++kd) {
        LDX4(qfh[kd][0], qfh[kd][1], qfh[kd][2], qfh[kd][3],
             sb + A_QH + (uint32_t)(wid * 16 + lmrow) * AROW + kd * 32 + lmk);
    }

    float o[8][4];
#pragma unroll
    for (int j = 0; j < 8; ++j)
#pragma unroll
        for (int r = 0; r < 4; ++r) o[j][r] = 0.f;
    float mstat[2] = {-1e30f, -1e30f};
    float lstat[2] = {0.f, 0.f};

    constexpr int NTT = Ss / 64;   // 32
    int s3 = 0;
    for (int t = 0; t < NTT; ++t) {
        if (t + 1 < NTT) { CP_WAIT(1); } else { CP_WAIT(0); }
        __syncthreads();
        if (t + 2 < NTT) {
            int sn = s3 + 2; if (sn >= 3) sn -= 3;
            issue_kv(t + 2, sn);
        }

        const uint32_t kvb = sb + A_KV0 + s3 * KVSTAGE;

        // ---- S = Q K^T ----
        float sreg[8][4];
#pragma unroll
        for (int j = 0; j < 8; ++j)
#pragma unroll
            for (int r = 0; r < 4; ++r) sreg[j][r] = 0.f;

#pragma unroll
        for (int kd = 0; kd < 4; ++kd) {
#pragma unroll
            for (int j16 = 0; j16 < 4; ++j16) {
                uint32_t h0, h1, h2, h3;
                LDX4(h0, h1, h2, h3,
                     kvb + (uint32_t)(j16 * 16 + lmrow) * AROW + kd * 32 + lmk);
                uint32_t bh0[2] = {h0, h2}, bh1[2] = {h1, h3};
                mma_f16(sreg[2 * j16],     qfh[kd], bh0);
                mma_f16(sreg[2 * j16 + 1], qfh[kd], bh1);
            }
        }

        // ---- online softmax ----
#pragma unroll
        for (int hf = 0; hf < 2; ++hf) {
            float mx = -1e30f;
#pragma unroll
            for (int j = 0; j < 8; ++j)
                mx = fmaxf(mx, fmaxf(sreg[j][hf * 2], sreg[j][hf * 2 + 1]));
            mx = fmaxf(mx, __shfl_xor_sync(0xffffffffu, mx, 1));
            mx = fmaxf(mx, __shfl_xor_sync(0xffffffffu, mx, 2));
            float mnew = fmaxf(mstat[hf], mx);
            float corr = __expf(mstat[hf] - mnew);
            float sum = 0.f;
#pragma unroll
            for (int j = 0; j < 8; ++j) {
                sreg[j][hf * 2]     = __expf(sreg[j][hf * 2] - mnew);
                sreg[j][hf * 2 + 1] = __expf(sreg[j][hf * 2 + 1] - mnew);
                sum += sreg[j][hf * 2] + sreg[j][hf * 2 + 1];
            }
            sum += __shfl_xor_sync(0xffffffffu, sum, 1);
            sum += __shfl_xor_sync(0xffffffffu, sum, 2);
            lstat[hf] = lstat[hf] * corr + sum;
            mstat[hf] = mnew;
#pragma unroll
            for (int j = 0; j < 8; ++j) {
                o[j][hf * 2]     *= corr;
                o[j][hf * 2 + 1] *= corr;
            }
        }

        // ---- O += P V ----
#pragma unroll
        for (int kk = 0; kk < 4; ++kk) {
            uint32_t ah[4];
            ah[0] = packf(sreg[2 * kk][0],     sreg[2 * kk][1]);
            ah[1] = packf(sreg[2 * kk][2],     sreg[2 * kk][3]);
            ah[2] = packf(sreg[2 * kk + 1][0], sreg[2 * kk + 1][1]);
            ah[3] = packf(sreg[2 * kk + 1][2], sreg[2 * kk + 1][3]);
#pragma unroll
            for (int j = 0; j < 4; ++j) {
                uint32_t vh0, vh1, vh2, vh3;
                LDX4T(vh0, vh1, vh2, vh3,
                      kvb + KV_ARR + (uint32_t)(kk * 16 + lmrow) * AROW + j * 32 + lmk);
                uint32_t bh0[2] = {vh0, vh1}, bh1[2] = {vh2, vh3};
                mma_f16(o[2 * j],     ah, bh0);
                mma_f16(o[2 * j + 1], ah, bh1);
            }
        }
        if (++s3 == 3) s3 = 0;
    }

    // epilogue: fp16 hi only
    const int g  = lane >> 2;
    const int tt = lane & 3;
    const float inv0 = 1.f / lstat[0];
    const float inv1 = 1.f / lstat[1];
    const int mrow = q0 + wid * 16 + g;
    uint32_t* ah0 = ah_g + (size_t)(b * Ss + mrow) * 1024 + h * 32;
    uint32_t* ah1 = ah0 + (size_t)8 * 1024;
#pragma unroll
    for (int j = 0; j < 8; ++j) {
        ah0[j * 4 + tt] = packf(o[j][0] * inv0, o[j][1] * inv0);
        ah1[j * 4 + tt] = packf(o[j][2] * inv1, o[j][3] * inv1);
    }
}

// ---------------------------------------------------------------------------
extern "C" void kernel_launch(void* const* d_in, const int* in_sizes, int n_in,
                              void* d_out, int out_size)
{
    (void)in_sizes; (void)n_in; (void)out_size;
    const float* x    = (const float*)d_in[0];
    const float* cosb = (const float*)d_in[1];
    const float* sinb = (const float*)d_in[2];
    const float* Wq   = (const float*)d_in[3];
    const float* Wk   = (const float*)d_in[4];
    const float* Wv   = (const float*)d_in[5];
    const float* Wo   = (const float*)d_in[6];
    float* out = (float*)d_out;

    void *xh, *xl, *wqh, *wkh, *wvh, *woh;
    void *qhp, *khp, *vhp, *ahp;
    cudaGetSymbolAddress(&xh, s_xh);   cudaGetSymbolAddress(&xl, s_xl);
    cudaGetSymbolAddress(&wqh, s_wqh); cudaGetSymbolAddress(&wkh, s_wkh);
    cudaGetSymbolAddress(&wvh, s_wvh); cudaGetSymbolAddress(&woh, s_woh);
    cudaGetSymbolAddress(&qhp, s_qh);
    cudaGetSymbolAddress(&khp, s_kh);  cudaGetSymbolAddress(&vhp, s_vh);
    cudaGetSymbolAddress(&ahp, s_ah);

    cudaFuncSetAttribute(proj_qkv_kernel, cudaFuncAttributeMaxDynamicSharedMemorySize, GB_SMEM);
    cudaFuncSetAttribute(gemm_out_kernel, cudaFuncAttributeMaxDynamicSharedMemorySize, G1_SMEM);
    cudaFuncSetAttribute(attn_mma_kernel, cudaFuncAttributeMaxDynamicSharedMemorySize, A_SMEM);

    // 1) pre-split x (hi+lo) and weights (hi)
    split_all_kernel<<<(N4_TOT + 255) / 256, 256>>>(
        (const float4*)x, (const float4*)Wq, (const float4*)Wk,
        (const float4*)Wv, (const float4*)Wo,
        (uint2*)xh, (uint2*)xl, (uint2*)wqh, (uint2*)wkh,
        (uint2*)wvh, (uint2*)woh);

    // 2) fused QKV projections with rope/split epilogues (one launch)
    proj_qkv_kernel<<<768, 256, GB_SMEM>>>(
        xh, xl, wqh, wkh, wvh, cosb, sinb,
        (uint32_t*)qhp, (uint32_t*)khp, (uint32_t*)vhp);

    // 3) attention
    attn_mma_kernel<<<dim3(16, 32, 2), 256, A_SMEM>>>(
        (const uint32_t*)qhp, (const uint32_t*)khp, (const uint32_t*)vhp,
        (uint32_t*)ahp);

    // 4) output projection (single-term)
    gemm_out_kernel<<<dim3(16, 32), 256, G1_SMEM>>>(ahp, woh, out);
}

// round 15
// speedup vs baseline: 1.6500x; 1.2333x over previous
#include <cuda_runtime.h>
#include <cuda_fp16.h>
#include <cstdint>
#include <math.h>

// Problem constants
constexpr int Bb  = 2;
constexpr int Ss  = 2048;
constexpr int Ee  = 2048;
constexpr int Hh  = 32;
constexpr int HKVv= 8;
constexpr int Dd  = 64;
constexpr int MS  = Bb * Ss;      // 4096 rows

// ---------------------------------------------------------------------------
// Scratch. fp16 pairs packed in uint32 (low half = even element).
// Everything single-term fp16-hi.
// ---------------------------------------------------------------------------
__device__ uint32_t s_xh[MS * Ee / 2];
__device__ uint32_t s_wqh[Ee * Ee / 2];
__device__ uint32_t s_wkh[512 * Ee / 2];
__device__ uint32_t s_wvh[512 * Ee / 2];
__device__ uint32_t s_woh[Ee * Ee / 2];
__device__ uint32_t s_qh[MS * 1024];
__device__ uint32_t s_kh[MS * 256];
__device__ uint32_t s_vh[MS * 256];
__device__ uint32_t s_ah[MS * 1024];

// ---------------------------------------------------------------------------
// Helpers
// ---------------------------------------------------------------------------
__device__ __forceinline__ uint32_t smem_u32(const void* p) {
    uint32_t a;
    asm("{ .reg .u64 t; cvta.to.shared.u64 t, %1; cvt.u32.u64 %0, t; }" : "=r"(a) : "l"(p));
    return a;
}

#define LDX4(r0, r1, r2, r3, addr) \
    asm volatile("ldmatrix.sync.aligned.m8n8.x4.shared.b16 {%0,%1,%2,%3}, [%4];" \
        : "=r"(r0), "=r"(r1), "=r"(r2), "=r"(r3) : "r"(addr))

#define LDX4T(r0, r1, r2, r3, addr) \
    asm volatile("ldmatrix.sync.aligned.m8n8.x4.trans.shared.b16 {%0,%1,%2,%3}, [%4];" \
        : "=r"(r0), "=r"(r1), "=r"(r2), "=r"(r3) : "r"(addr))

#define CP_ASYNC16(dst, src) \
    asm volatile("cp.async.cg.shared.global [%0], [%1], 16;" :: "r"(dst), "l"(src))
#define CP_COMMIT() asm volatile("cp.async.commit_group;")
#define CP_WAIT(n)  asm volatile("cp.async.wait_group %0;" :: "n"(n))

__device__ __forceinline__ void mma_f16(float c[4], const uint32_t a[4], const uint32_t b[2]) {
    asm volatile("mma.sync.aligned.m16n8k16.row.col.f32.f16.f16.f32 "
                 "{%0,%1,%2,%3}, {%4,%5,%6,%7}, {%8,%9}, {%0,%1,%2,%3};"
                 : "+f"(c[0]), "+f"(c[1]), "+f"(c[2]), "+f"(c[3])
                 : "r"(a[0]), "r"(a[1]), "r"(a[2]), "r"(a[3]), "r"(b[0]), "r"(b[1]));
}

__device__ __forceinline__ uint32_t packf(float x0, float x1) {
    __half2 h = __floats2half2_rn(x0, x1);
    return *reinterpret_cast<uint32_t*>(&h);
}

// ---------------------------------------------------------------------------
// Fused split kernel: all inputs -> fp16 hi. One launch.
// ---------------------------------------------------------------------------
constexpr int N4_X  = MS * Ee / 4;
constexpr int N4_WQ = Ee * Ee / 4;
constexpr int N4_WK = 512 * Ee / 4;
constexpr int N4_TOT = N4_X + N4_WQ + 2 * N4_WK + N4_WQ;

__global__ void split_all_kernel(
    const float4* __restrict__ x,  const float4* __restrict__ wq,
    const float4* __restrict__ wk, const float4* __restrict__ wv,
    const float4* __restrict__ wo,
    uint2* __restrict__ xh,  uint2* __restrict__ wqh, uint2* __restrict__ wkh,
    uint2* __restrict__ wvh, uint2* __restrict__ woh)
{
    int i = blockIdx.x * blockDim.x + threadIdx.x;
    if (i >= N4_TOT) return;
    const float4* src; uint2* hi; int j = i;
    if (j < N4_X)                   { src = x;  hi = xh;  }
    else if ((j -= N4_X)  < N4_WQ)  { src = wq; hi = wqh; }
    else if ((j -= N4_WQ) < N4_WK)  { src = wk; hi = wkh; }
    else if ((j -= N4_WK) < N4_WK)  { src = wv; hi = wvh; }
    else { j -= N4_WK;                src = wo; hi = woh; }
    float4 f = src[j];
    hi[j] = make_uint2(packf(f.x, f.y), packf(f.z, f.w));
}

// ---------------------------------------------------------------------------
// Single-term fp16 GEMM mainloop: warp tile 32x64, BK=32, 4-stage cp.async,
// 2 CTAs/SM, single sync per stage. 64B rows, XOR swizzle.
// ---------------------------------------------------------------------------
constexpr int GB_TILE  = 128 * 64;         // 8192
constexpr int G1_STAGE = 2 * GB_TILE;      // 16384 (Ah, Bh)
constexpr int G1_SMEM  = 4 * G1_STAGE;     // 65536; 2 CTAs/SM

__device__ __forceinline__ uint32_t swz(uint32_t row, uint32_t chunk) {
    return row * 64 + ((chunk ^ ((row >> 1) & 3)) << 4);
}

__device__ __forceinline__ void gemm_mainloop_1t(
    const char* Ah, const char* Bh,
    int m0, int n0, char* smem, float acc[2][8][4])
{
    const uint32_t sbase = smem_u32(smem);
    const int tid  = threadIdx.x;
    const int wid  = tid >> 5;
    const int lane = tid & 31;
    const int wm = wid & 3;
    const int wn = wid >> 2;
    const int lmrow = lane & 15;
    const int lmc   = lane >> 4;

#pragma unroll
    for (int i = 0; i < 2; ++i)
#pragma unroll
        for (int j = 0; j < 8; ++j)
#pragma unroll
            for (int r = 0; r < 4; ++r) acc[i][j][r] = 0.f;

    auto issue = [&](int kt, int s) {
#pragma unroll
        for (int c = 0; c < 4; ++c) {
            int ch  = c * 256 + tid;
            int arr = ch >> 9;          // 0=Ah 1=Bh
            int r   = (ch >> 2) & 127;
            int c16 = ch & 3;
            const char* g = (arr == 0)
                ? Ah + (size_t)(m0 + r) * 4096 + kt * 64 + c16 * 16
                : Bh + (size_t)(n0 + r) * 4096 + kt * 64 + c16 * 16;
            uint32_t dst = sbase + s * G1_STAGE + arr * GB_TILE + swz(r, c16);
            CP_ASYNC16(dst, g);
        }
        CP_COMMIT();
    };

    issue(0, 0);
    issue(1, 1);
    issue(2, 2);

    constexpr int NT = 64;
    for (int kt = 0; kt < NT; ++kt) {
        const int s = kt & 3;
        if (kt + 2 < NT)      { CP_WAIT(2); }
        else if (kt + 1 < NT) { CP_WAIT(1); }
        else                  { CP_WAIT(0); }
        __syncthreads();
        if (kt + 3 < NT) issue(kt + 3, (kt + 3) & 3);

        const uint32_t tb = sbase + s * G1_STAGE;
#pragma unroll
        for (int ks = 0; ks < 2; ++ks) {
            const uint32_t kchunk = ks * 2 + lmc;
            uint32_t bh[8][2];
#pragma unroll
            for (int g16 = 0; g16 < 4; ++g16) {
                uint32_t r0, r1, r2, r3;
                LDX4(r0, r1, r2, r3,
                     tb + GB_TILE + swz(wn * 64 + g16 * 16 + lmrow, kchunk));
                bh[g16 * 2][0] = r0; bh[g16 * 2][1] = r2;
                bh[g16 * 2 + 1][0] = r1; bh[g16 * 2 + 1][1] = r3;
            }
            uint32_t afh[2][4];
#pragma unroll
            for (int mt = 0; mt < 2; ++mt)
                LDX4(afh[mt][0], afh[mt][1], afh[mt][2], afh[mt][3],
                     tb + swz(wm * 32 + mt * 16 + lmrow, kchunk));
#pragma unroll
            for (int mt = 0; mt < 2; ++mt)
#pragma unroll
                for (int nt = 0; nt < 8; ++nt)
                    mma_f16(acc[mt][nt], afh[mt], bh[nt]);
        }
    }
}

// ---------------------------------------------------------------------------
// Fused QKV projection: one launch, 768 CTAs. Q pre-scaled by 0.125, hi only.
// ---------------------------------------------------------------------------
__global__ void __launch_bounds__(256, 2) proj_qkv_kernel(
    const void* xh_,
    const void* wqh_, const void* wkh_, const void* wvh_,
    const float* __restrict__ cosb, const float* __restrict__ sinb,
    uint32_t* __restrict__ qh,
    uint32_t* __restrict__ kh, uint32_t* __restrict__ vh)
{
    extern __shared__ char smem[];
    const char* xh = (const char*)xh_;
    const int id = blockIdx.x;
    const int tid  = threadIdx.x;
    const int wid  = tid >> 5;
    const int lane = tid & 31;
    const int wm = wid & 3;
    const int wn = wid >> 2;
    const int g  = lane >> 2;
    const int tq = lane & 3;

    float acc[2][8][4];

    if (id < 512) {
        const int m0 = (id >> 4) * 128;
        const int n0 = (id & 15) * 128;
        gemm_mainloop_1t(xh, (const char*)wqh_, m0, n0, smem, acc);
        const int head = (n0 + wn * 64) >> 6;
#pragma unroll
        for (int mt = 0; mt < 2; ++mt) {
#pragma unroll
            for (int rr = 0; rr < 2; ++rr) {
                int row = m0 + wm * 32 + mt * 16 + g + rr * 8;
                int s = row & (Ss - 1);
                const float* cb  = cosb + s * 64;
                const float* sb2 = sinb + s * 64;
                uint32_t* qh_p = qh + (size_t)row * 1024 + head * 32;
#pragma unroll
                for (int nt = 0; nt < 4; ++nt) {
                    int d = nt * 8 + tq * 2;
                    float2 c1 = *(const float2*)(cb + d);
                    float2 s1 = *(const float2*)(sb2 + d);
                    float2 c2 = *(const float2*)(cb + d + 32);
                    float2 s2 = *(const float2*)(sb2 + d + 32);
                    float x10 = acc[mt][nt][rr * 2],     x11 = acc[mt][nt][rr * 2 + 1];
                    float x20 = acc[mt][nt + 4][rr * 2], x21 = acc[mt][nt + 4][rr * 2 + 1];
                    float y0 = (x10 * c1.x - x20 * s1.x) * 0.125f;
                    float y1 = (x11 * c1.y - x21 * s1.y) * 0.125f;
                    float y2 = (x20 * c2.x + x10 * s2.x) * 0.125f;
                    float y3 = (x21 * c2.y + x11 * s2.y) * 0.125f;
                    qh_p[nt * 4 + tq]      = packf(y0, y1);
                    qh_p[16 + nt * 4 + tq] = packf(y2, y3);
                }
            }
        }
    } else if (id < 640) {
        const int id2 = id - 512;
        const int m0 = (id2 >> 2) * 128;
        const int n0 = (id2 & 3) * 128;
        gemm_mainloop_1t(xh, (const char*)wkh_, m0, n0, smem, acc);
        const int head = (n0 + wn * 64) >> 6;
#pragma unroll
        for (int mt = 0; mt < 2; ++mt) {
#pragma unroll
            for (int rr = 0; rr < 2; ++rr) {
                int row = m0 + wm * 32 + mt * 16 + g + rr * 8;
                int s = row & (Ss - 1);
                const float* cb  = cosb + s * 64;
                const float* sb2 = sinb + s * 64;
                uint32_t* kh_p = kh + (size_t)row * 256 + head * 32;
#pragma unroll
                for (int nt = 0; nt < 4; ++nt) {
                    int d = nt * 8 + tq * 2;
                    float2 c1 = *(const float2*)(cb + d);
                    float2 s1 = *(const float2*)(sb2 + d);
                    float2 c2 = *(const float2*)(cb + d + 32);
                    float2 s2 = *(const float2*)(sb2 + d + 32);
                    float x10 = acc[mt][nt][rr * 2],     x11 = acc[mt][nt][rr * 2 + 1];
                    float x20 = acc[mt][nt + 4][rr * 2], x21 = acc[mt][nt + 4][rr * 2 + 1];
                    float y0 = x10 * c1.x - x20 * s1.x;
                    float y1 = x11 * c1.y - x21 * s1.y;
                    float y2 = x20 * c2.x + x10 * s2.x;
                    float y3 = x21 * c2.y + x11 * s2.y;
                    kh_p[nt * 4 + tq]      = packf(y0, y1);
                    kh_p[16 + nt * 4 + tq] = packf(y2, y3);
                }
            }
        }
    } else {
        const int id2 = id - 640;
        const int m0 = (id2 >> 2) * 128;
        const int n0 = (id2 & 3) * 128;
        gemm_mainloop_1t(xh, (const char*)wvh_, m0, n0, smem, acc);
        const int cp0 = (n0 + wn * 64) >> 1;
#pragma unroll
        for (int mt = 0; mt < 2; ++mt) {
#pragma unroll
            for (int rr = 0; rr < 2; ++rr) {
                int row = m0 + wm * 32 + mt * 16 + g + rr * 8;
                uint32_t* vh_p = vh + (size_t)row * 256 + cp0;
#pragma unroll
                for (int nt = 0; nt < 8; ++nt)
                    vh_p[nt * 4 + tq] = packf(acc[mt][nt][rr * 2], acc[mt][nt][rr * 2 + 1]);
            }
        }
    }
}

// ---------------------------------------------------------------------------
// O projection (single-term): fp32 output to d_out.
// ---------------------------------------------------------------------------
__global__ void __launch_bounds__(256, 2) gemm_out_kernel(
    const void* Ah, const void* Bh, float* C)
{
    extern __shared__ char smem[];
    const int tid  = threadIdx.x;
    const int wid  = tid >> 5;
    const int lane = tid & 31;
    const int m0 = blockIdx.y * 128;
    const int n0 = blockIdx.x * 128;
    const int wm = wid & 3;
    const int wn = wid >> 2;
    float acc[2][8][4];
    gemm_mainloop_1t((const char*)Ah, (const char*)Bh, m0, n0, smem, acc);
    const int g = lane >> 2;
    const int t = lane & 3;
#pragma unroll
    for (int mt = 0; mt < 2; ++mt) {
#pragma unroll
        for (int nt = 0; nt < 8; ++nt) {
            int r = m0 + wm * 32 + mt * 16 + g;
            int c = n0 + wn * 64 + nt * 8 + t * 2;
            *(float2*)(C + (size_t)r * 2048 + c)       = make_float2(acc[mt][nt][0], acc[mt][nt][1]);
            *(float2*)(C + (size_t)(r + 8) * 2048 + c) = make_float2(acc[mt][nt][2], acc[mt][nt][3]);
        }
    }
}

// ---------------------------------------------------------------------------
// Flash attention. QK: single-term Qh*Kh (Q pre-scaled). PV: single-term.
// Epilogue writes fp16 hi only. 3-stage KV cp.async, single sync per tile.
// ---------------------------------------------------------------------------
constexpr int AROW   = 144;
constexpr int A_QH   = 0;
constexpr int A_KV0  = A_QH + 128 * AROW;      // 18432
constexpr int KV_ARR = 64 * AROW;              // 9216 (KH, VH)
constexpr int KVSTAGE = 2 * KV_ARR;            // 18432
constexpr int A_SMEM  = A_KV0 + 3 * KVSTAGE;   // 73728

__global__ void __launch_bounds__(256, 1) attn_mma_kernel(
    const uint32_t* __restrict__ qh_g,
    const uint32_t* __restrict__ kh_g, const uint32_t* __restrict__ vh_g,
    uint32_t* __restrict__ ah_g)
{
    extern __shared__ char sm[];
    const uint32_t sb = smem_u32(sm);
    const int tid  = threadIdx.x;
    const int wid  = tid >> 5;
    const int lane = tid & 31;
    const int q0 = blockIdx.x * 128;
    const int h  = blockIdx.y;
    const int b  = blockIdx.z;
    const int hkv = h >> 2;

    const int lmrow  = lane & 15;
    const int lmk    = (lane >> 4) * 16;

    auto issue_kv = [&](int t, int s) {
#pragma unroll
        for (int c = 0; c < 4; ++c) {
            int ch  = c * 256 + tid;
            int arr = ch >> 9;
            int r   = (ch >> 3) & 63;
            int c16 = ch & 7;
            const uint32_t* gsrc = arr ? vh_g : kh_g;
            const char* g = (const char*)gsrc
                + ((size_t)(b * Ss + t * 64 + r) * 256 + hkv * 32) * 4 + c16 * 16;
            uint32_t dst = sb + A_KV0 + s * KVSTAGE + arr * KV_ARR + r * AROW + c16 * 16;
            CP_ASYNC16(dst, g);
        }
        CP_COMMIT();
    };

    issue_kv(0, 0);
    issue_kv(1, 1);

#pragma unroll
    for (int c = 0; c < 4; ++c) {
        int ch  = c * 256 + tid;
        int r   = ch >> 3;
        int c16 = ch & 7;
        const char* src = (const char*)qh_g
            + ((size_t)(b * Ss + q0 + r) * 1024 + h * 32) * 4 + c16 * 16;
        *(uint4*)(sm + A_QH + r * AROW + c16 * 16) = *(const uint4*)src;
    }
    __syncthreads();

    uint32_t qfh[4][4];
#pragma unroll
    for (int kd = 0; kd < 4; ++kd) {
        LDX4(qfh[kd][0], qfh[kd][1], qfh[kd][2], qfh[kd][3],
             sb + A_QH + (uint32_t)(wid * 16 + lmrow) * AROW + kd * 32 + lmk);
    }

    float o[8][4];
#pragma unroll
    for (int j = 0; j < 8; ++j)
#pragma unroll
        for (int r = 0; r < 4; ++r) o[j][r] = 0.f;
    float mstat[2] = {-1e30f, -1e30f};
    float lstat[2] = {0.f, 0.f};

    constexpr int NTT = Ss / 64;   // 32
    int s3 = 0;
    for (int t = 0; t < NTT; ++t) {
        if (t + 1 < NTT) { CP_WAIT(1); } else { CP_WAIT(0); }
        __syncthreads();
        if (t + 2 < NTT) {
            int sn = s3 + 2; if (sn >= 3) sn -= 3;
            issue_kv(t + 2, sn);
        }

        const uint32_t kvb = sb + A_KV0 + s3 * KVSTAGE;

        float sreg[8][4];
#pragma unroll
        for (int j = 0; j < 8; ++j)
#pragma unroll
            for (int r = 0; r < 4; ++r) sreg[j][r] = 0.f;

#pragma unroll
        for (int kd = 0; kd < 4; ++kd) {
#pragma unroll
            for (int j16 = 0; j16 < 4; ++j16) {
                uint32_t h0, h1, h2, h3;
                LDX4(h0, h1, h2, h3,
                     kvb + (uint32_t)(j16 * 16 + lmrow) * AROW + kd * 32 + lmk);
                uint32_t bh0[2] = {h0, h2}, bh1[2] = {h1, h3};
                mma_f16(sreg[2 * j16],     qfh[kd], bh0);
                mma_f16(sreg[2 * j16 + 1], qfh[kd], bh1);
            }
        }

#pragma unroll
        for (int hf = 0; hf < 2; ++hf) {
            float mx = -1e30f;
#pragma unroll
            for (int j = 0; j < 8; ++j)
                mx = fmaxf(mx, fmaxf(sreg[j][hf * 2], sreg[j][hf * 2 + 1]));
            mx = fmaxf(mx, __shfl_xor_sync(0xffffffffu, mx, 1));
            mx = fmaxf(mx, __shfl_xor_sync(0xffffffffu, mx, 2));
            float mnew = fmaxf(mstat[hf], mx);
            float corr = __expf(mstat[hf] - mnew);
            float sum = 0.f;
#pragma unroll
            for (int j = 0; j < 8; ++j) {
                sreg[j][hf * 2]     = __expf(sreg[j][hf * 2] - mnew);
                sreg[j][hf * 2 + 1] = __expf(sreg[j][hf * 2 + 1] - mnew);
                sum += sreg[j][hf * 2] + sreg[j][hf * 2 + 1];
            }
            sum += __shfl_xor_sync(0xffffffffu, sum, 1);
            sum += __shfl_xor_sync(0xffffffffu, sum, 2);
            lstat[hf] = lstat[hf] * corr + sum;
            mstat[hf] = mnew;
#pragma unroll
            for (int j = 0; j < 8; ++j) {
                o[j][hf * 2]     *= corr;
                o[j][hf * 2 + 1] *= corr;
            }
        }

#pragma unroll
        for (int kk = 0; kk < 4; ++kk) {
            uint32_t ah[4];
            ah[0] = packf(sreg[2 * kk][0],     sreg[2 * kk][1]);
            ah[1] = packf(sreg[2 * kk][2],     sreg[2 * kk][3]);
            ah[2] = packf(sreg[2 * kk + 1][0], sreg[2 * kk + 1][1]);
            ah[3] = packf(sreg[2 * kk + 1][2], sreg[2 * kk + 1][3]);
#pragma unroll
            for (int j = 0; j < 4; ++j) {
                uint32_t vh0, vh1, vh2, vh3;
                LDX4T(vh0, vh1, vh2, vh3,
                      kvb + KV_ARR + (uint32_t)(kk * 16 + lmrow) * AROW + j * 32 + lmk);
                uint32_t bh0[2] = {vh0, vh1}, bh1[2] = {vh2, vh3};
                mma_f16(o[2 * j],     ah, bh0);
                mma_f16(o[2 * j + 1], ah, bh1);
            }
        }
        if (++s3 == 3) s3 = 0;
    }

    const int g  = lane >> 2;
    const int tt = lane & 3;
    const float inv0 = 1.f / lstat[0];
    const float inv1 = 1.f / lstat[1];
    const int mrow = q0 + wid * 16 + g;
    uint32_t* ah0 = ah_g + (size_t)(b * Ss + mrow) * 1024 + h * 32;
    uint32_t* ah1 = ah0 + (size_t)8 * 1024;
#pragma unroll
    for (int j = 0; j < 8; ++j) {
        ah0[j * 4 + tt] = packf(o[j][0] * inv0, o[j][1] * inv0);
        ah1[j * 4 + tt] = packf(o[j][2] * inv1, o[j][3] * inv1);
    }
}

// ---------------------------------------------------------------------------
extern "C" void kernel_launch(void* const* d_in, const int* in_sizes, int n_in,
                              void* d_out, int out_size)
{
    (void)in_sizes; (void)n_in; (void)out_size;
    const float* x    = (const float*)d_in[0];
    const float* cosb = (const float*)d_in[1];
    const float* sinb = (const float*)d_in[2];
    const float* Wq   = (const float*)d_in[3];
    const float* Wk   = (const float*)d_in[4];
    const float* Wv   = (const float*)d_in[5];
    const float* Wo   = (const float*)d_in[6];
    float* out = (float*)d_out;

    void *xh, *wqh, *wkh, *wvh, *woh;
    void *qhp, *khp, *vhp, *ahp;
    cudaGetSymbolAddress(&xh, s_xh);
    cudaGetSymbolAddress(&wqh, s_wqh); cudaGetSymbolAddress(&wkh, s_wkh);
    cudaGetSymbolAddress(&wvh, s_wvh); cudaGetSymbolAddress(&woh, s_woh);
    cudaGetSymbolAddress(&qhp, s_qh);
    cudaGetSymbolAddress(&khp, s_kh);  cudaGetSymbolAddress(&vhp, s_vh);
    cudaGetSymbolAddress(&ahp, s_ah);

    cudaFuncSetAttribute(proj_qkv_kernel, cudaFuncAttributeMaxDynamicSharedMemorySize, G1_SMEM);
    cudaFuncSetAttribute(gemm_out_kernel, cudaFuncAttributeMaxDynamicSharedMemorySize, G1_SMEM);
    cudaFuncSetAttribute(attn_mma_kernel, cudaFuncAttributeMaxDynamicSharedMemorySize, A_SMEM);

    // 1) pre-split x and weights to fp16 hi
    split_all_kernel<<<(N4_TOT + 255) / 256, 256>>>(
        (const float4*)x, (const float4*)Wq, (const float4*)Wk,
        (const float4*)Wv, (const float4*)Wo,
        (uint2*)xh, (uint2*)wqh, (uint2*)wkh, (uint2*)wvh, (uint2*)woh);

    // 2) fused QKV projections with rope/split epilogues (one launch)
    proj_qkv_kernel<<<768, 256, G1_SMEM>>>(
        xh, wqh, wkh, wvh, cosb, sinb,
        (uint32_t*)qhp, (uint32_t*)khp, (uint32_t*)vhp);

    // 3) attention
    attn_mma_kernel<<<dim3(16, 32, 2), 256, A_SMEM>>>(
        (const uint32_t*)qhp, (const uint32_t*)khp, (const uint32_t*)vhp,
        (uint32_t*)ahp);

    // 4) output projection (single-term)
    gemm_out_kernel<<<dim3(16, 32), 256, G1_SMEM>>>(ahp, woh, out);
}

// round 16
// speedup vs baseline: 1.7887x; 1.0841x over previous
#include <cuda_runtime.h>
#include <cuda_fp16.h>
#include <cstdint>
#include <math.h>

// Problem constants
constexpr int Bb  = 2;
constexpr int Ss  = 2048;
constexpr int Ee  = 2048;
constexpr int Hh  = 32;
constexpr int HKVv= 8;
constexpr int Dd  = 64;
constexpr int MS  = Bb * Ss;      // 4096 rows

// ---------------------------------------------------------------------------
// Scratch. fp16 pairs packed in uint32 (low half = even element).
// Everything single-term fp16-hi.
// ---------------------------------------------------------------------------
__device__ uint32_t s_xh[MS * Ee / 2];
__device__ uint32_t s_wqh[Ee * Ee / 2];
__device__ uint32_t s_wkh[512 * Ee / 2];
__device__ uint32_t s_wvh[512 * Ee / 2];
__device__ uint32_t s_woh[Ee * Ee / 2];
__device__ uint32_t s_qh[MS * 1024];
__device__ uint32_t s_kh[MS * 256];
__device__ uint32_t s_vh[MS * 256];
__device__ uint32_t s_ah[MS * 1024];

// ---------------------------------------------------------------------------
// Helpers
// ---------------------------------------------------------------------------
__device__ __forceinline__ uint32_t smem_u32(const void* p) {
    uint32_t a;
    asm("{ .reg .u64 t; cvta.to.shared.u64 t, %1; cvt.u32.u64 %0, t; }" : "=r"(a) : "l"(p));
    return a;
}

#define LDX4(r0, r1, r2, r3, addr) \
    asm volatile("ldmatrix.sync.aligned.m8n8.x4.shared.b16 {%0,%1,%2,%3}, [%4];" \
        : "=r"(r0), "=r"(r1), "=r"(r2), "=r"(r3) : "r"(addr))

#define LDX4T(r0, r1, r2, r3, addr) \
    asm volatile("ldmatrix.sync.aligned.m8n8.x4.trans.shared.b16 {%0,%1,%2,%3}, [%4];" \
        : "=r"(r0), "=r"(r1), "=r"(r2), "=r"(r3) : "r"(addr))

#define CP_ASYNC16(dst, src) \
    asm volatile("cp.async.cg.shared.global [%0], [%1], 16;" :: "r"(dst), "l"(src))
#define CP_COMMIT() asm volatile("cp.async.commit_group;")
#define CP_WAIT(n)  asm volatile("cp.async.wait_group %0;" :: "n"(n))

__device__ __forceinline__ void mma_f16(float c[4], const uint32_t a[4], const uint32_t b[2]) {
    asm volatile("mma.sync.aligned.m16n8k16.row.col.f32.f16.f16.f32 "
                 "{%0,%1,%2,%3}, {%4,%5,%6,%7}, {%8,%9}, {%0,%1,%2,%3};"
                 : "+f"(c[0]), "+f"(c[1]), "+f"(c[2]), "+f"(c[3])
                 : "r"(a[0]), "r"(a[1]), "r"(a[2]), "r"(a[3]), "r"(b[0]), "r"(b[1]));
}

__device__ __forceinline__ uint32_t packf(float x0, float x1) {
    __half2 h = __floats2half2_rn(x0, x1);
    return *reinterpret_cast<uint32_t*>(&h);
}

// ---------------------------------------------------------------------------
// Fused split kernel: all inputs -> fp16 hi. One launch.
// ---------------------------------------------------------------------------
constexpr int N4_X  = MS * Ee / 4;
constexpr int N4_WQ = Ee * Ee / 4;
constexpr int N4_WK = 512 * Ee / 4;
constexpr int N4_TOT = N4_X + N4_WQ + 2 * N4_WK + N4_WQ;

__global__ void split_all_kernel(
    const float4* __restrict__ x,  const float4* __restrict__ wq,
    const float4* __restrict__ wk, const float4* __restrict__ wv,
    const float4* __restrict__ wo,
    uint2* __restrict__ xh,  uint2* __restrict__ wqh, uint2* __restrict__ wkh,
    uint2* __restrict__ wvh, uint2* __restrict__ woh)
{
    int i = blockIdx.x * blockDim.x + threadIdx.x;
    if (i >= N4_TOT) return;
    const float4* src; uint2* hi; int j = i;
    if (j < N4_X)                   { src = x;  hi = xh;  }
    else if ((j -= N4_X)  < N4_WQ)  { src = wq; hi = wqh; }
    else if ((j -= N4_WQ) < N4_WK)  { src = wk; hi = wkh; }
    else if ((j -= N4_WK) < N4_WK)  { src = wv; hi = wvh; }
    else { j -= N4_WK;                src = wo; hi = woh; }
    float4 f = src[j];
    hi[j] = make_uint2(packf(f.x, f.y), packf(f.z, f.w));
}

// ---------------------------------------------------------------------------
// Single-term fp16 GEMM mainloop: warp tile 32x64, BK=32, 4-stage cp.async,
// 2 CTAs/SM, single sync per stage. 64B rows, XOR swizzle.
// ---------------------------------------------------------------------------
constexpr int GB_TILE  = 128 * 64;         // 8192
constexpr int G1_STAGE = 2 * GB_TILE;      // 16384 (Ah, Bh)
constexpr int G1_SMEM  = 4 * G1_STAGE;     // 65536; 2 CTAs/SM

__device__ __forceinline__ uint32_t swz(uint32_t row, uint32_t chunk) {
    return row * 64 + ((chunk ^ ((row >> 1) & 3)) << 4);
}

__device__ __forceinline__ void gemm_mainloop_1t(
    const char* Ah, const char* Bh,
    int m0, int n0, char* smem, float acc[2][8][4])
{
    const uint32_t sbase = smem_u32(smem);
    const int tid  = threadIdx.x;
    const int wid  = tid >> 5;
    const int lane = tid & 31;
    const int wm = wid & 3;
    const int wn = wid >> 2;
    const int lmrow = lane & 15;
    const int lmc   = lane >> 4;

#pragma unroll
    for (int i = 0; i < 2; ++i)
#pragma unroll
        for (int j = 0; j < 8; ++j)
#pragma unroll
            for (int r = 0; r < 4; ++r) acc[i][j][r] = 0.f;

    auto issue = [&](int kt, int s) {
#pragma unroll
        for (int c = 0; c < 4; ++c) {
            int ch  = c * 256 + tid;
            int arr = ch >> 9;          // 0=Ah 1=Bh
            int r   = (ch >> 2) & 127;
            int c16 = ch & 3;
            const char* g = (arr == 0)
                ? Ah + (size_t)(m0 + r) * 4096 + kt * 64 + c16 * 16
                : Bh + (size_t)(n0 + r) * 4096 + kt * 64 + c16 * 16;
            uint32_t dst = sbase + s * G1_STAGE + arr * GB_TILE + swz(r, c16);
            CP_ASYNC16(dst, g);
        }
        CP_COMMIT();
    };

    issue(0, 0);
    issue(1, 1);
    issue(2, 2);

    constexpr int NT = 64;
    for (int kt = 0; kt < NT; ++kt) {
        const int s = kt & 3;
        if (kt + 2 < NT)      { CP_WAIT(2); }
        else if (kt + 1 < NT) { CP_WAIT(1); }
        else                  { CP_WAIT(0); }
        __syncthreads();
        if (kt + 3 < NT) issue(kt + 3, (kt + 3) & 3);

        const uint32_t tb = sbase + s * G1_STAGE;
#pragma unroll
        for (int ks = 0; ks < 2; ++ks) {
            const uint32_t kchunk = ks * 2 + lmc;
            uint32_t bh[8][2];
#pragma unroll
            for (int g16 = 0; g16 < 4; ++g16) {
                uint32_t r0, r1, r2, r3;
                LDX4(r0, r1, r2, r3,
                     tb + GB_TILE + swz(wn * 64 + g16 * 16 + lmrow, kchunk));
                bh[g16 * 2][0] = r0; bh[g16 * 2][1] = r2;
                bh[g16 * 2 + 1][0] = r1; bh[g16 * 2 + 1][1] = r3;
            }
            uint32_t afh[2][4];
#pragma unroll
            for (int mt = 0; mt < 2; ++mt)
                LDX4(afh[mt][0], afh[mt][1], afh[mt][2], afh[mt][3],
                     tb + swz(wm * 32 + mt * 16 + lmrow, kchunk));
#pragma unroll
            for (int mt = 0; mt < 2; ++mt)
#pragma unroll
                for (int nt = 0; nt < 8; ++nt)
                    mma_f16(acc[mt][nt], afh[mt], bh[nt]);
        }
    }
}

// ---------------------------------------------------------------------------
// Fused QKV projection: one launch, 768 CTAs. Q pre-scaled by 0.125, hi only.
// ---------------------------------------------------------------------------
__global__ void __launch_bounds__(256, 2) proj_qkv_kernel(
    const void* xh_,
    const void* wqh_, const void* wkh_, const void* wvh_,
    const float* __restrict__ cosb, const float* __restrict__ sinb,
    uint32_t* __restrict__ qh,
    uint32_t* __restrict__ kh, uint32_t* __restrict__ vh)
{
    extern __shared__ char smem[];
    const char* xh = (const char*)xh_;
    const int id = blockIdx.x;
    const int tid  = threadIdx.x;
    const int wid  = tid >> 5;
    const int lane = tid & 31;
    const int wm = wid & 3;
    const int wn = wid >> 2;
    const int g  = lane >> 2;
    const int tq = lane & 3;

    float acc[2][8][4];

    if (id < 512) {
        const int m0 = (id >> 4) * 128;
        const int n0 = (id & 15) * 128;
        gemm_mainloop_1t(xh, (const char*)wqh_, m0, n0, smem, acc);
        const int head = (n0 + wn * 64) >> 6;
#pragma unroll
        for (int mt = 0; mt < 2; ++mt) {
#pragma unroll
            for (int rr = 0; rr < 2; ++rr) {
                int row = m0 + wm * 32 + mt * 16 + g + rr * 8;
                int s = row & (Ss - 1);
                const float* cb  = cosb + s * 64;
                const float* sb2 = sinb + s * 64;
                uint32_t* qh_p = qh + (size_t)row * 1024 + head * 32;
#pragma unroll
                for (int nt = 0; nt < 4; ++nt) {
                    int d = nt * 8 + tq * 2;
                    float2 c1 = *(const float2*)(cb + d);
                    float2 s1 = *(const float2*)(sb2 + d);
                    float2 c2 = *(const float2*)(cb + d + 32);
                    float2 s2 = *(const float2*)(sb2 + d + 32);
                    float x10 = acc[mt][nt][rr * 2],     x11 = acc[mt][nt][rr * 2 + 1];
                    float x20 = acc[mt][nt + 4][rr * 2], x21 = acc[mt][nt + 4][rr * 2 + 1];
                    float y0 = (x10 * c1.x - x20 * s1.x) * 0.125f;
                    float y1 = (x11 * c1.y - x21 * s1.y) * 0.125f;
                    float y2 = (x20 * c2.x + x10 * s2.x) * 0.125f;
                    float y3 = (x21 * c2.y + x11 * s2.y) * 0.125f;
                    qh_p[nt * 4 + tq]      = packf(y0, y1);
                    qh_p[16 + nt * 4 + tq] = packf(y2, y3);
                }
            }
        }
    } else if (id < 640) {
        const int id2 = id - 512;
        const int m0 = (id2 >> 2) * 128;
        const int n0 = (id2 & 3) * 128;
        gemm_mainloop_1t(xh, (const char*)wkh_, m0, n0, smem, acc);
        const int head = (n0 + wn * 64) >> 6;
#pragma unroll
        for (int mt = 0; mt < 2; ++mt) {
#pragma unroll
            for (int rr = 0; rr < 2; ++rr) {
                int row = m0 + wm * 32 + mt * 16 + g + rr * 8;
                int s = row & (Ss - 1);
                const float* cb  = cosb + s * 64;
                const float* sb2 = sinb + s * 64;
                uint32_t* kh_p = kh + (size_t)row * 256 + head * 32;
#pragma unroll
                for (int nt = 0; nt < 4; ++nt) {
                    int d = nt * 8 + tq * 2;
                    float2 c1 = *(const float2*)(cb + d);
                    float2 s1 = *(const float2*)(sb2 + d);
                    float2 c2 = *(const float2*)(cb + d + 32);
                    float2 s2 = *(const float2*)(sb2 + d + 32);
                    float x10 = acc[mt][nt][rr * 2],     x11 = acc[mt][nt][rr * 2 + 1];
                    float x20 = acc[mt][nt + 4][rr * 2], x21 = acc[mt][nt + 4][rr * 2 + 1];
                    float y0 = x10 * c1.x - x20 * s1.x;
                    float y1 = x11 * c1.y - x21 * s1.y;
                    float y2 = x20 * c2.x + x10 * s2.x;
                    float y3 = x21 * c2.y + x11 * s2.y;
                    kh_p[nt * 4 + tq]      = packf(y0, y1);
                    kh_p[16 + nt * 4 + tq] = packf(y2, y3);
                }
            }
        }
    } else {
        const int id2 = id - 640;
        const int m0 = (id2 >> 2) * 128;
        const int n0 = (id2 & 3) * 128;
        gemm_mainloop_1t(xh, (const char*)wvh_, m0, n0, smem, acc);
        const int cp0 = (n0 + wn * 64) >> 1;
#pragma unroll
        for (int mt = 0; mt < 2; ++mt) {
#pragma unroll
            for (int rr = 0; rr < 2; ++rr) {
                int row = m0 + wm * 32 + mt * 16 + g + rr * 8;
                uint32_t* vh_p = vh + (size_t)row * 256 + cp0;
#pragma unroll
                for (int nt = 0; nt < 8; ++nt)
                    vh_p[nt * 4 + tq] = packf(acc[mt][nt][rr * 2], acc[mt][nt][rr * 2 + 1]);
            }
        }
    }
}

// ---------------------------------------------------------------------------
// O projection (single-term): fp32 output to d_out.
// ---------------------------------------------------------------------------
__global__ void __launch_bounds__(256, 2) gemm_out_kernel(
    const void* Ah, const void* Bh, float* C)
{
    extern __shared__ char smem[];
    const int tid  = threadIdx.x;
    const int wid  = tid >> 5;
    const int lane = tid & 31;
    const int m0 = blockIdx.y * 128;
    const int n0 = blockIdx.x * 128;
    const int wm = wid & 3;
    const int wn = wid >> 2;
    float acc[2][8][4];
    gemm_mainloop_1t((const char*)Ah, (const char*)Bh, m0, n0, smem, acc);
    const int g = lane >> 2;
    const int t = lane & 3;
#pragma unroll
    for (int mt = 0; mt < 2; ++mt) {
#pragma unroll
        for (int nt = 0; nt < 8; ++nt) {
            int r = m0 + wm * 32 + mt * 16 + g;
            int c = n0 + wn * 64 + nt * 8 + t * 2;
            *(float2*)(C + (size_t)r * 2048 + c)       = make_float2(acc[mt][nt][0], acc[mt][nt][1]);
            *(float2*)(C + (size_t)(r + 8) * 2048 + c) = make_float2(acc[mt][nt][2], acc[mt][nt][3]);
        }
    }
}

// ---------------------------------------------------------------------------
// Flash attention. QK: single-term Qh*Kh (Q pre-scaled). PV: single-term.
// NOW 2 CTAs/SM: cross-CTA overlap of softmax (FMA/MUFU) with MMA.
// 3-stage KV cp.async, single sync per tile.
// ---------------------------------------------------------------------------
constexpr int AROW   = 144;
constexpr int A_QH   = 0;
constexpr int A_KV0  = A_QH + 128 * AROW;      // 18432
constexpr int KV_ARR = 64 * AROW;              // 9216 (KH, VH)
constexpr int KVSTAGE = 2 * KV_ARR;            // 18432
constexpr int A_SMEM  = A_KV0 + 3 * KVSTAGE;   // 73728; x2 CTAs = 147456/SM

__global__ void __launch_bounds__(256, 2) attn_mma_kernel(
    const uint32_t* __restrict__ qh_g,
    const uint32_t* __restrict__ kh_g, const uint32_t* __restrict__ vh_g,
    uint32_t* __restrict__ ah_g)
{
    extern __shared__ char sm[];
    const uint32_t sb = smem_u32(sm);
    const int tid  = threadIdx.x;
    const int wid  = tid >> 5;
    const int lane = tid & 31;
    const int q0 = blockIdx.x * 128;
    const int h  = blockIdx.y;
    const int b  = blockIdx.z;
    const int hkv = h >> 2;

    const int lmrow  = lane & 15;
    const int lmk    = (lane >> 4) * 16;

    auto issue_kv = [&](int t, int s) {
#pragma unroll
        for (int c = 0; c < 4; ++c) {
            int ch  = c * 256 + tid;
            int arr = ch >> 9;
            int r   = (ch >> 3) & 63;
            int c16 = ch & 7;
            const uint32_t* gsrc = arr ? vh_g : kh_g;
            const char* g = (const char*)gsrc
                + ((size_t)(b * Ss + t * 64 + r) * 256 + hkv * 32) * 4 + c16 * 16;
            uint32_t dst = sb + A_KV0 + s * KVSTAGE + arr * KV_ARR + r * AROW + c16 * 16;
            CP_ASYNC16(dst, g);
        }
        CP_COMMIT();
    };

    issue_kv(0, 0);
    issue_kv(1, 1);

#pragma unroll
    for (int c = 0; c < 4; ++c) {
        int ch  = c * 256 + tid;
        int r   = ch >> 3;
        int c16 = ch & 7;
        const char* src = (const char*)qh_g
            + ((size_t)(b * Ss + q0 + r) * 1024 + h * 32) * 4 + c16 * 16;
        *(uint4*)(sm + A_QH + r * AROW + c16 * 16) = *(const uint4*)src;
    }
    __syncthreads();

    uint32_t qfh[4][4];
#pragma unroll
    for (int kd = 0; kd < 4; ++kd) {
        LDX4(qfh[kd][0], qfh[kd][1], qfh[kd][2], qfh[kd][3],
             sb + A_QH + (uint32_t)(wid * 16 + lmrow) * AROW + kd * 32 + lmk);
    }

    float o[8][4];
#pragma unroll
    for (int j = 0; j < 8; ++j)
#pragma unroll
        for (int r = 0; r < 4; ++r) o[j][r] = 0.f;
    float mstat[2] = {-1e30f, -1e30f};
    float lstat[2] = {0.f, 0.f};

    constexpr int NTT = Ss / 64;   // 32
    int s3 = 0;
    for (int t = 0; t < NTT; ++t) {
        if (t + 1 < NTT) { CP_WAIT(1); } else { CP_WAIT(0); }
        __syncthreads();
        if (t + 2 < NTT) {
            int sn = s3 + 2; if (sn >= 3) sn -= 3;
            issue_kv(t + 2, sn);
        }

        const uint32_t kvb = sb + A_KV0 + s3 * KVSTAGE;

        float sreg[8][4];
#pragma unroll
        for (int j = 0; j < 8; ++j)
#pragma unroll
            for (int r = 0; r < 4; ++r) sreg[j][r] = 0.f;

#pragma unroll
        for (int kd = 0; kd < 4; ++kd) {
#pragma unroll
            for (int j16 = 0; j16 < 4; ++j16) {
                uint32_t h0, h1, h2, h3;
                LDX4(h0, h1, h2, h3,
                     kvb + (uint32_t)(j16 * 16 + lmrow) * AROW + kd * 32 + lmk);
                uint32_t bh0[2] = {h0, h2}, bh1[2] = {h1, h3};
                mma_f16(sreg[2 * j16],     qfh[kd], bh0);
                mma_f16(sreg[2 * j16 + 1], qfh[kd], bh1);
            }
        }

#pragma unroll
        for (int hf = 0; hf < 2; ++hf) {
            float mx = -1e30f;
#pragma unroll
            for (int j = 0; j < 8; ++j)
                mx = fmaxf(mx, fmaxf(sreg[j][hf * 2], sreg[j][hf * 2 + 1]));
            mx = fmaxf(mx, __shfl_xor_sync(0xffffffffu, mx, 1));
            mx = fmaxf(mx, __shfl_xor_sync(0xffffffffu, mx, 2));
            float mnew = fmaxf(mstat[hf], mx);
            float corr = __expf(mstat[hf] - mnew);
            float sum = 0.f;
#pragma unroll
            for (int j = 0; j < 8; ++j) {
                sreg[j][hf * 2]     = __expf(sreg[j][hf * 2] - mnew);
                sreg[j][hf * 2 + 1] = __expf(sreg[j][hf * 2 + 1] - mnew);
                sum += sreg[j][hf * 2] + sreg[j][hf * 2 + 1];
            }
            sum += __shfl_xor_sync(0xffffffffu, sum, 1);
            sum += __shfl_xor_sync(0xffffffffu, sum, 2);
            lstat[hf] = lstat[hf] * corr + sum;
            mstat[hf] = mnew;
#pragma unroll
            for (int j = 0; j < 8; ++j) {
                o[j][hf * 2]     *= corr;
                o[j][hf * 2 + 1] *= corr;
            }
        }

#pragma unroll
        for (int kk = 0; kk < 4; ++kk) {
            uint32_t ah[4];
            ah[0] = packf(sreg[2 * kk][0],     sreg[2 * kk][1]);
            ah[1] = packf(sreg[2 * kk][2],     sreg[2 * kk][3]);
            ah[2] = packf(sreg[2 * kk + 1][0], sreg[2 * kk + 1][1]);
            ah[3] = packf(sreg[2 * kk + 1][2], sreg[2 * kk + 1][3]);
#pragma unroll
            for (int j = 0; j < 4; ++j) {
                uint32_t vh0, vh1, vh2, vh3;
                LDX4T(vh0, vh1, vh2, vh3,
                      kvb + KV_ARR + (uint32_t)(kk * 16 + lmrow) * AROW + j * 32 + lmk);
                uint32_t bh0[2] = {vh0, vh1}, bh1[2] = {vh2, vh3};
                mma_f16(o[2 * j],     ah, bh0);
                mma_f16(o[2 * j + 1], ah, bh1);
            }
        }
        if (++s3 == 3) s3 = 0;
    }

    const int g  = lane >> 2;
    const int tt = lane & 3;
    const float inv0 = 1.f / lstat[0];
    const float inv1 = 1.f / lstat[1];
    const int mrow = q0 + wid * 16 + g;
    uint32_t* ah0 = ah_g + (size_t)(b * Ss + mrow) * 1024 + h * 32;
    uint32_t* ah1 = ah0 + (size_t)8 * 1024;
#pragma unroll
    for (int j = 0; j < 8; ++j) {
        ah0[j * 4 + tt] = packf(o[j][0] * inv0, o[j][1] * inv0);
        ah1[j * 4 + tt] = packf(o[j][2] * inv1, o[j][3] * inv1);
    }
}

// ---------------------------------------------------------------------------
extern "C" void kernel_launch(void* const* d_in, const int* in_sizes, int n_in,
                              void* d_out, int out_size)
{
    (void)in_sizes; (void)n_in; (void)out_size;
    const float* x    = (const float*)d_in[0];
    const float* cosb = (const float*)d_in[1];
    const float* sinb = (const float*)d_in[2];
    const float* Wq   = (const float*)d_in[3];
    const float* Wk   = (const float*)d_in[4];
    const float* Wv   = (const float*)d_in[5];
    const float* Wo   = (const float*)d_in[6];
    float* out = (float*)d_out;

    void *xh, *wqh, *wkh, *wvh, *woh;
    void *qhp, *khp, *vhp, *ahp;
    cudaGetSymbolAddress(&xh, s_xh);
    cudaGetSymbolAddress(&wqh, s_wqh); cudaGetSymbolAddress(&wkh, s_wkh);
    cudaGetSymbolAddress(&wvh, s_wvh); cudaGetSymbolAddress(&woh, s_woh);
    cudaGetSymbolAddress(&qhp, s_qh);
    cudaGetSymbolAddress(&khp, s_kh);  cudaGetSymbolAddress(&vhp, s_vh);
    cudaGetSymbolAddress(&ahp, s_ah);

    cudaFuncSetAttribute(proj_qkv_kernel, cudaFuncAttributeMaxDynamicSharedMemorySize, G1_SMEM);
    cudaFuncSetAttribute(gemm_out_kernel, cudaFuncAttributeMaxDynamicSharedMemorySize, G1_SMEM);
    cudaFuncSetAttribute(attn_mma_kernel, cudaFuncAttributeMaxDynamicSharedMemorySize, A_SMEM);

    // 1) pre-split x and weights to fp16 hi
    split_all_kernel<<<(N4_TOT + 255) / 256, 256>>>(
        (const float4*)x, (const float4*)Wq, (const float4*)Wk,
        (const float4*)Wv, (const float4*)Wo,
        (uint2*)xh, (uint2*)wqh, (uint2*)wkh, (uint2*)wvh, (uint2*)woh);

    // 2) fused QKV projections with rope/split epilogues (one launch)
    proj_qkv_kernel<<<768, 256, G1_SMEM>>>(
        xh, wqh, wkh, wvh, cosb, sinb,
        (uint32_t*)qhp, (uint32_t*)khp, (uint32_t*)vhp);

    // 3) attention (2 CTAs/SM)
    attn_mma_kernel<<<dim3(16, 32, 2), 256, A_SMEM>>>(
        (const uint32_t*)qhp, (const uint32_t*)khp, (const uint32_t*)vhp,
        (uint32_t*)ahp);

    // 4) output projection (single-term)
    gemm_out_kernel<<<dim3(16, 32), 256, G1_SMEM>>>(ahp, woh, out);
}